// round 1
// baseline (speedup 1.0000x reference)
#include <cuda_runtime.h>

#define BB 2
#define S  2048
#define H  16
#define D  1024
#define DK 64
#define MROWS (BB*S)   // 4096

#define QT 16          // query rows per attention block
#define KT 256         // key/value rows per smem tile

// Scratch (device globals — allocation-free per harness rules)
__device__ float g_Q[BB*H*S*DK];    // [B,H,S,DK]
__device__ float g_K[BB*H*S*DK];
__device__ float g_V[BB*H*S*DK];
__device__ float g_ctx[MROWS*D];    // attention context, row-major [B*S, D]

// ---------------------------------------------------------------------------
// Kernel 1: fused QKV projection. grid = (16, 64, 3); 256 threads.
// C[m,n] = X[m,:] @ W[:,n] + bias[n], stored head-major into g_Q/g_K/g_V.
// 64x64 tile, BK=16, 4x4 register micro-tile per thread.
// ---------------------------------------------------------------------------
__global__ __launch_bounds__(256) void qkv_kernel(
    const float* __restrict__ Xq, const float* __restrict__ Xk, const float* __restrict__ Xv,
    const float* __restrict__ Wq, const float* __restrict__ Wk, const float* __restrict__ Wv,
    const float* __restrict__ bq, const float* __restrict__ bk, const float* __restrict__ bv)
{
    __shared__ float sA[16][65];   // [k][m] transposed
    __shared__ float sB[16][65];   // [k][n]

    const int z = blockIdx.z;
    const float* X    = (z == 0) ? Xq : (z == 1) ? Xk : Xv;
    const float* W    = (z == 0) ? Wq : (z == 1) ? Wk : Wv;
    const float* bias = (z == 0) ? bq : (z == 1) ? bk : bv;
    float* out        = (z == 0) ? g_Q : (z == 1) ? g_K : g_V;

    const int tid = threadIdx.x;
    const int m0 = blockIdx.y * 64;
    const int n0 = blockIdx.x * 64;
    const int ty = tid / 16, tx = tid % 16;

    const int lm  = tid >> 2;    // 0..63  (A row)
    const int lk4 = tid & 3;     // 0..3   (A k-group of 4)
    const int lkB = tid >> 4;    // 0..15  (B k row)
    const int ln4 = tid & 15;    // 0..15  (B n-group of 4)

    float c[4][4] = {};

    for (int kb = 0; kb < D; kb += 16) {
        float4 av = *(const float4*)&X[(size_t)(m0 + lm) * D + kb + 4 * lk4];
        float4 wv = *(const float4*)&W[(size_t)(kb + lkB) * D + n0 + 4 * ln4];
        __syncthreads();
        sA[4*lk4+0][lm] = av.x; sA[4*lk4+1][lm] = av.y;
        sA[4*lk4+2][lm] = av.z; sA[4*lk4+3][lm] = av.w;
        sB[lkB][4*ln4+0] = wv.x; sB[lkB][4*ln4+1] = wv.y;
        sB[lkB][4*ln4+2] = wv.z; sB[lkB][4*ln4+3] = wv.w;
        __syncthreads();
        #pragma unroll
        for (int kk = 0; kk < 16; kk++) {
            float a[4], b_[4];
            #pragma unroll
            for (int i = 0; i < 4; i++) a[i]  = sA[kk][ty + 16*i];
            #pragma unroll
            for (int j = 0; j < 4; j++) b_[j] = sB[kk][tx + 16*j];
            #pragma unroll
            for (int i = 0; i < 4; i++)
                #pragma unroll
                for (int j = 0; j < 4; j++)
                    c[i][j] += a[i] * b_[j];
        }
    }

    #pragma unroll
    for (int i = 0; i < 4; i++) {
        #pragma unroll
        for (int j = 0; j < 4; j++) {
            int m = m0 + ty + 16*i;
            int n = n0 + tx + 16*j;
            float v = c[i][j] + bias[n];
            int b = m >> 11, s = m & 2047;     // m / 2048, m % 2048
            int h = n >> 6,  d = n & 63;
            out[(size_t)((b * H + h) * S + s) * DK + d] = v;
        }
    }
}

// ---------------------------------------------------------------------------
// Kernel 2: attention. grid = (S/QT, B*H); 256 threads; dynamic smem.
// Keeps the full 16x2048 score strip in SMEM: scores -> softmax -> write attn
// (single DRAM write) -> AV into g_ctx.
// ---------------------------------------------------------------------------
#define SMEM_ATTN_FLOATS (QT*S + KT*65 + QT*DK)   // 32768 + 16640 + 1024 = 50432
#define SMEM_ATTN_BYTES  (SMEM_ATTN_FLOATS * 4)   // 201728 B

__global__ __launch_bounds__(256) void attn_kernel(float* __restrict__ attn_out)
{
    extern __shared__ float sm[];
    float* sS = sm;                    // [QT][S]
    float* sK = sm + QT * S;           // [KT][65]  (K tile, then V tile, then reduce buf)
    float* sQ = sK + KT * 65;          // [QT][DK]

    const int tid = threadIdx.x;
    const int bh  = blockIdx.y;              // b*H + h
    const int q0  = blockIdx.x * QT;

    const float* Qp = g_Q + ((size_t)bh * S + q0) * DK;
    const float* Kp = g_K + (size_t)bh * S * DK;
    const float* Vp = g_V + (size_t)bh * S * DK;

    // load Q tile (16x64)
    {
        int qi = tid >> 4, d4 = tid & 15;
        float4 v = *(const float4*)&Qp[qi * DK + 4 * d4];
        *(float4*)&sQ[qi * DK + 4 * d4] = v;
    }

    const int l  = tid & 63;    // key lane within tile
    const int qg = tid >> 6;    // query group 0..3
    const float scale = 0.125f; // 1/sqrt(64)

    // ---- Phase 1: S = Q @ K^T * scale, into sS ----
    for (int kt = 0; kt < S; kt += KT) {
        // load K tile 256x64 (coalesced global, scalar STS into padded rows)
        #pragma unroll
        for (int r = 0; r < 16; r++) {
            int row = r * 16 + (tid >> 4);
            int d4  = tid & 15;
            float4 v = *(const float4*)&Kp[(size_t)(kt + row) * DK + 4 * d4];
            sK[row * 65 + 4*d4 + 0] = v.x; sK[row * 65 + 4*d4 + 1] = v.y;
            sK[row * 65 + 4*d4 + 2] = v.z; sK[row * 65 + 4*d4 + 3] = v.w;
        }
        __syncthreads();

        float acc[4][4] = {};
        #pragma unroll 8
        for (int d = 0; d < DK; d++) {
            float kv[4], qv[4];
            #pragma unroll
            for (int j = 0; j < 4; j++) kv[j] = sK[(l + 64*j) * 65 + d];
            #pragma unroll
            for (int i = 0; i < 4; i++) qv[i] = sQ[(qg*4 + i) * DK + d];
            #pragma unroll
            for (int i = 0; i < 4; i++)
                #pragma unroll
                for (int j = 0; j < 4; j++)
                    acc[i][j] += qv[i] * kv[j];
        }
        #pragma unroll
        for (int i = 0; i < 4; i++)
            #pragma unroll
            for (int j = 0; j < 4; j++)
                sS[(qg*4 + i) * S + kt + l + 64*j] = acc[i][j] * scale;
        __syncthreads();
    }

    // ---- Phase 2: softmax in place + single write of attn ----
    {
        int w = tid >> 5, lane = tid & 31;
        #pragma unroll
        for (int rr = 0; rr < 2; rr++) {
            int r = w * 2 + rr;
            float* row = sS + r * S;
            float mx = -1e30f;
            for (int c2 = lane; c2 < S; c2 += 32) mx = fmaxf(mx, row[c2]);
            #pragma unroll
            for (int o = 16; o; o >>= 1) mx = fmaxf(mx, __shfl_xor_sync(0xffffffffu, mx, o));
            float sum = 0.f;
            for (int c2 = lane; c2 < S; c2 += 32) {
                float p = __expf(row[c2] - mx);
                row[c2] = p;
                sum += p;
            }
            #pragma unroll
            for (int o = 16; o; o >>= 1) sum += __shfl_xor_sync(0xffffffffu, sum, o);
            float inv = 1.0f / sum;
            float* arow = attn_out + ((size_t)bh * S + q0 + r) * S;
            for (int c2 = lane; c2 < S; c2 += 32) {
                float p = row[c2] * inv;
                row[c2] = p;
                arow[c2] = p;
            }
        }
    }
    __syncthreads();

    // ---- Phase 3: O = P @ V  (4-way split over k, then reduce) ----
    const int t   = tid & 63;
    const int grp = tid >> 6;       // k-range group 0..3
    const int dj  = t & 15;         // d column base
    const int qb  = t >> 4;         // query base 0..3
    float acc2[4][4] = {};

    for (int vt = 0; vt < S; vt += KT) {
        // load V tile 256x64 into sK
        #pragma unroll
        for (int r = 0; r < 16; r++) {
            int row = r * 16 + (tid >> 4);
            int d4  = tid & 15;
            float4 v = *(const float4*)&Vp[(size_t)(vt + row) * DK + 4 * d4];
            sK[row * 65 + 4*d4 + 0] = v.x; sK[row * 65 + 4*d4 + 1] = v.y;
            sK[row * 65 + 4*d4 + 2] = v.z; sK[row * 65 + 4*d4 + 3] = v.w;
        }
        __syncthreads();

        int kbase = vt + grp * 64;
        #pragma unroll 8
        for (int kk = 0; kk < 64; kk++) {
            float pv[4], vv[4];
            #pragma unroll
            for (int i = 0; i < 4; i++) pv[i] = sS[(qb + 4*i) * S + kbase + kk];
            #pragma unroll
            for (int j = 0; j < 4; j++) vv[j] = sK[(grp*64 + kk) * 65 + dj + 16*j];
            #pragma unroll
            for (int i = 0; i < 4; i++)
                #pragma unroll
                for (int j = 0; j < 4; j++)
                    acc2[i][j] += pv[i] * vv[j];
        }
        __syncthreads();
    }

    // reduce 4 partial groups via sK (V tiles no longer needed)
    float* red = sK;    // 4 * 1024 floats
    #pragma unroll
    for (int i = 0; i < 4; i++)
        #pragma unroll
        for (int j = 0; j < 4; j++)
            red[grp * (QT*DK) + (qb + 4*i) * DK + dj + 16*j] = acc2[i][j];
    __syncthreads();

    const int b = bh >> 4, h = bh & 15;
    for (int e = tid; e < QT * DK; e += 256) {
        float v = red[e] + red[QT*DK + e] + red[2*QT*DK + e] + red[3*QT*DK + e];
        int qi = e >> 6, d = e & 63;
        g_ctx[((size_t)(b * S) + q0 + qi) * D + h * DK + d] = v;
    }
}

// ---------------------------------------------------------------------------
// Kernel 3: output projection. out = g_ctx @ Wo + bo  (row-major to d_out)
// ---------------------------------------------------------------------------
__global__ __launch_bounds__(256) void oproj_kernel(
    const float* __restrict__ Wo, const float* __restrict__ bo, float* __restrict__ out)
{
    __shared__ float sA[16][65];
    __shared__ float sB[16][65];

    const int tid = threadIdx.x;
    const int m0 = blockIdx.y * 64;
    const int n0 = blockIdx.x * 64;
    const int ty = tid / 16, tx = tid % 16;

    const int lm  = tid >> 2;
    const int lk4 = tid & 3;
    const int lkB = tid >> 4;
    const int ln4 = tid & 15;

    float c[4][4] = {};

    for (int kb = 0; kb < D; kb += 16) {
        float4 av = *(const float4*)&g_ctx[(size_t)(m0 + lm) * D + kb + 4 * lk4];
        float4 wv = *(const float4*)&Wo[(size_t)(kb + lkB) * D + n0 + 4 * ln4];
        __syncthreads();
        sA[4*lk4+0][lm] = av.x; sA[4*lk4+1][lm] = av.y;
        sA[4*lk4+2][lm] = av.z; sA[4*lk4+3][lm] = av.w;
        sB[lkB][4*ln4+0] = wv.x; sB[lkB][4*ln4+1] = wv.y;
        sB[lkB][4*ln4+2] = wv.z; sB[lkB][4*ln4+3] = wv.w;
        __syncthreads();
        #pragma unroll
        for (int kk = 0; kk < 16; kk++) {
            float a[4], b_[4];
            #pragma unroll
            for (int i = 0; i < 4; i++) a[i]  = sA[kk][ty + 16*i];
            #pragma unroll
            for (int j = 0; j < 4; j++) b_[j] = sB[kk][tx + 16*j];
            #pragma unroll
            for (int i = 0; i < 4; i++)
                #pragma unroll
                for (int j = 0; j < 4; j++)
                    c[i][j] += a[i] * b_[j];
        }
    }

    #pragma unroll
    for (int i = 0; i < 4; i++)
        #pragma unroll
        for (int j = 0; j < 4; j++) {
            int m = m0 + ty + 16*i;
            int n = n0 + tx + 16*j;
            out[(size_t)m * D + n] = c[i][j] + bo[n];
        }
}

// ---------------------------------------------------------------------------
extern "C" void kernel_launch(void* const* d_in, const int* in_sizes, int n_in,
                              void* d_out, int out_size)
{
    const float* query = (const float*)d_in[0];
    const float* key   = (const float*)d_in[1];
    const float* value = (const float*)d_in[2];
    const float* Wq    = (const float*)d_in[3];
    const float* bq    = (const float*)d_in[4];
    const float* Wk    = (const float*)d_in[5];
    const float* bk    = (const float*)d_in[6];
    const float* Wv    = (const float*)d_in[7];
    const float* bv    = (const float*)d_in[8];
    const float* Wo    = (const float*)d_in[9];
    const float* bo    = (const float*)d_in[10];

    float* out  = (float*)d_out;                      // [B,S,D]
    float* attn = out + (size_t)MROWS * D;            // [B,H,S,S]

    cudaFuncSetAttribute(attn_kernel, cudaFuncAttributeMaxDynamicSharedMemorySize,
                         SMEM_ATTN_BYTES);

    qkv_kernel<<<dim3(D/64, MROWS/64, 3), 256>>>(query, key, value,
                                                 Wq, Wk, Wv, bq, bk, bv);
    attn_kernel<<<dim3(S/QT, BB*H), 256, SMEM_ATTN_BYTES>>>(attn);
    oproj_kernel<<<dim3(D/64, MROWS/64), 256>>>(Wo, bo, out);
}

// round 2
// speedup vs baseline: 1.0066x; 1.0066x over previous
#include <cuda_runtime.h>

#define BB 2
#define S  2048
#define H  16
#define D  1024
#define DK 64
#define MROWS (BB*S)   // 4096

#define QT 16          // query rows per attention block
#define KT 256         // key/value rows per smem tile

// Scratch (device globals — allocation-free per harness rules)
__device__ float g_Q[BB*H*S*DK];    // [B,H,S,DK]
__device__ float g_K[BB*H*S*DK];
__device__ float g_V[BB*H*S*DK];
__device__ float g_ctx[MROWS*D];    // attention context, row-major [B*S, D]

// ---------------------------------------------------------------------------
// Kernel 1: fused QKV projection. grid = (16, 64, 3); 256 threads.
// C[m,n] = X[m,:] @ W[:,n] + bias[n], stored head-major into g_Q/g_K/g_V.
// 64x64 tile, BK=16, 4x4 register micro-tile per thread.
// ---------------------------------------------------------------------------
__global__ __launch_bounds__(256) void qkv_kernel(
    const float* __restrict__ Xq, const float* __restrict__ Xk, const float* __restrict__ Xv,
    const float* __restrict__ Wq, const float* __restrict__ Wk, const float* __restrict__ Wv,
    const float* __restrict__ bq, const float* __restrict__ bk, const float* __restrict__ bv)
{
    __shared__ float sA[16][65];   // [k][m] transposed
    __shared__ float sB[16][65];   // [k][n]

    const int z = blockIdx.z;
    const float* X    = (z == 0) ? Xq : (z == 1) ? Xk : Xv;
    const float* W    = (z == 0) ? Wq : (z == 1) ? Wk : Wv;
    const float* bias = (z == 0) ? bq : (z == 1) ? bk : bv;
    float* out        = (z == 0) ? g_Q : (z == 1) ? g_K : g_V;

    const int tid = threadIdx.x;
    const int m0 = blockIdx.y * 64;
    const int n0 = blockIdx.x * 64;
    const int ty = tid / 16, tx = tid % 16;

    const int lm  = tid >> 2;    // 0..63  (A row)
    const int lk4 = tid & 3;     // 0..3   (A k-group of 4)
    const int lkB = tid >> 4;    // 0..15  (B k row)
    const int ln4 = tid & 15;    // 0..15  (B n-group of 4)

    float c[4][4] = {};

    for (int kb = 0; kb < D; kb += 16) {
        float4 av = *(const float4*)&X[(size_t)(m0 + lm) * D + kb + 4 * lk4];
        float4 wv = *(const float4*)&W[(size_t)(kb + lkB) * D + n0 + 4 * ln4];
        __syncthreads();
        sA[4*lk4+0][lm] = av.x; sA[4*lk4+1][lm] = av.y;
        sA[4*lk4+2][lm] = av.z; sA[4*lk4+3][lm] = av.w;
        sB[lkB][4*ln4+0] = wv.x; sB[lkB][4*ln4+1] = wv.y;
        sB[lkB][4*ln4+2] = wv.z; sB[lkB][4*ln4+3] = wv.w;
        __syncthreads();
        #pragma unroll
        for (int kk = 0; kk < 16; kk++) {
            float a[4], b_[4];
            #pragma unroll
            for (int i = 0; i < 4; i++) a[i]  = sA[kk][ty + 16*i];
            #pragma unroll
            for (int j = 0; j < 4; j++) b_[j] = sB[kk][tx + 16*j];
            #pragma unroll
            for (int i = 0; i < 4; i++)
                #pragma unroll
                for (int j = 0; j < 4; j++)
                    c[i][j] += a[i] * b_[j];
        }
    }

    #pragma unroll
    for (int i = 0; i < 4; i++) {
        #pragma unroll
        for (int j = 0; j < 4; j++) {
            int m = m0 + ty + 16*i;
            int n = n0 + tx + 16*j;
            float v = c[i][j] + bias[n];
            int b = m >> 11, s = m & 2047;     // m / 2048, m % 2048
            int h = n >> 6,  d = n & 63;
            out[(size_t)((b * H + h) * S + s) * DK + d] = v;
        }
    }
}

// ---------------------------------------------------------------------------
// Kernel 2: attention. grid = (S/QT, B*H); 256 threads; dynamic smem.
// Keeps the full 16x2048 score strip in SMEM: scores -> softmax -> write attn
// (single DRAM write) -> AV into g_ctx.
// ---------------------------------------------------------------------------
#define SMEM_ATTN_FLOATS (QT*S + KT*65 + QT*DK)   // 32768 + 16640 + 1024 = 50432
#define SMEM_ATTN_BYTES  (SMEM_ATTN_FLOATS * 4)   // 201728 B

__global__ __launch_bounds__(256) void attn_kernel(float* __restrict__ attn_out)
{
    extern __shared__ float sm[];
    float* sS = sm;                    // [QT][S]
    float* sK = sm + QT * S;           // [KT][65]  (K tile, then V tile, then reduce buf)
    float* sQ = sK + KT * 65;          // [QT][DK]

    const int tid = threadIdx.x;
    const int bh  = blockIdx.y;              // b*H + h
    const int q0  = blockIdx.x * QT;

    const float* Qp = g_Q + ((size_t)bh * S + q0) * DK;
    const float* Kp = g_K + (size_t)bh * S * DK;
    const float* Vp = g_V + (size_t)bh * S * DK;

    // load Q tile (16x64)
    {
        int qi = tid >> 4, d4 = tid & 15;
        float4 v = *(const float4*)&Qp[qi * DK + 4 * d4];
        *(float4*)&sQ[qi * DK + 4 * d4] = v;
    }

    const int l  = tid & 63;    // key lane within tile
    const int qg = tid >> 6;    // query group 0..3
    const float scale = 0.125f; // 1/sqrt(64)

    // ---- Phase 1: S = Q @ K^T * scale, into sS ----
    for (int kt = 0; kt < S; kt += KT) {
        // load K tile 256x64 (coalesced global, scalar STS into padded rows)
        #pragma unroll
        for (int r = 0; r < 16; r++) {
            int row = r * 16 + (tid >> 4);
            int d4  = tid & 15;
            float4 v = *(const float4*)&Kp[(size_t)(kt + row) * DK + 4 * d4];
            sK[row * 65 + 4*d4 + 0] = v.x; sK[row * 65 + 4*d4 + 1] = v.y;
            sK[row * 65 + 4*d4 + 2] = v.z; sK[row * 65 + 4*d4 + 3] = v.w;
        }
        __syncthreads();

        float acc[4][4] = {};
        #pragma unroll 8
        for (int d = 0; d < DK; d++) {
            float kv[4], qv[4];
            #pragma unroll
            for (int j = 0; j < 4; j++) kv[j] = sK[(l + 64*j) * 65 + d];
            #pragma unroll
            for (int i = 0; i < 4; i++) qv[i] = sQ[(qg*4 + i) * DK + d];
            #pragma unroll
            for (int i = 0; i < 4; i++)
                #pragma unroll
                for (int j = 0; j < 4; j++)
                    acc[i][j] += qv[i] * kv[j];
        }
        #pragma unroll
        for (int i = 0; i < 4; i++)
            #pragma unroll
            for (int j = 0; j < 4; j++)
                sS[(qg*4 + i) * S + kt + l + 64*j] = acc[i][j] * scale;
        __syncthreads();
    }

    // ---- Phase 2: softmax in place + single write of attn ----
    {
        int w = tid >> 5, lane = tid & 31;
        #pragma unroll
        for (int rr = 0; rr < 2; rr++) {
            int r = w * 2 + rr;
            float* row = sS + r * S;
            float mx = -1e30f;
            for (int c2 = lane; c2 < S; c2 += 32) mx = fmaxf(mx, row[c2]);
            #pragma unroll
            for (int o = 16; o; o >>= 1) mx = fmaxf(mx, __shfl_xor_sync(0xffffffffu, mx, o));
            float sum = 0.f;
            for (int c2 = lane; c2 < S; c2 += 32) {
                float p = __expf(row[c2] - mx);
                row[c2] = p;
                sum += p;
            }
            #pragma unroll
            for (int o = 16; o; o >>= 1) sum += __shfl_xor_sync(0xffffffffu, sum, o);
            float inv = 1.0f / sum;
            float* arow = attn_out + ((size_t)bh * S + q0 + r) * S;
            for (int c2 = lane; c2 < S; c2 += 32) {
                float p = row[c2] * inv;
                row[c2] = p;
                arow[c2] = p;
            }
        }
    }
    __syncthreads();

    // ---- Phase 3: O = P @ V  (4-way split over k, then reduce) ----
    const int t   = tid & 63;
    const int grp = tid >> 6;       // k-range group 0..3
    const int dj  = t & 15;         // d column base
    const int qb  = t >> 4;         // query base 0..3
    float acc2[4][4] = {};

    for (int vt = 0; vt < S; vt += KT) {
        // load V tile 256x64 into sK
        #pragma unroll
        for (int r = 0; r < 16; r++) {
            int row = r * 16 + (tid >> 4);
            int d4  = tid & 15;
            float4 v = *(const float4*)&Vp[(size_t)(vt + row) * DK + 4 * d4];
            sK[row * 65 + 4*d4 + 0] = v.x; sK[row * 65 + 4*d4 + 1] = v.y;
            sK[row * 65 + 4*d4 + 2] = v.z; sK[row * 65 + 4*d4 + 3] = v.w;
        }
        __syncthreads();

        int kbase = vt + grp * 64;
        #pragma unroll 8
        for (int kk = 0; kk < 64; kk++) {
            float pv[4], vv[4];
            #pragma unroll
            for (int i = 0; i < 4; i++) pv[i] = sS[(qb + 4*i) * S + kbase + kk];
            #pragma unroll
            for (int j = 0; j < 4; j++) vv[j] = sK[(grp*64 + kk) * 65 + dj + 16*j];
            #pragma unroll
            for (int i = 0; i < 4; i++)
                #pragma unroll
                for (int j = 0; j < 4; j++)
                    acc2[i][j] += pv[i] * vv[j];
        }
        __syncthreads();
    }

    // reduce 4 partial groups via sK (V tiles no longer needed)
    float* red = sK;    // 4 * 1024 floats
    #pragma unroll
    for (int i = 0; i < 4; i++)
        #pragma unroll
        for (int j = 0; j < 4; j++)
            red[grp * (QT*DK) + (qb + 4*i) * DK + dj + 16*j] = acc2[i][j];
    __syncthreads();

    const int b = bh >> 4, h = bh & 15;
    for (int e = tid; e < QT * DK; e += 256) {
        float v = red[e] + red[QT*DK + e] + red[2*QT*DK + e] + red[3*QT*DK + e];
        int qi = e >> 6, d = e & 63;
        g_ctx[((size_t)(b * S) + q0 + qi) * D + h * DK + d] = v;
    }
}

// ---------------------------------------------------------------------------
// Kernel 3: output projection. out = g_ctx @ Wo + bo  (row-major to d_out)
// ---------------------------------------------------------------------------
__global__ __launch_bounds__(256) void oproj_kernel(
    const float* __restrict__ Wo, const float* __restrict__ bo, float* __restrict__ out)
{
    __shared__ float sA[16][65];
    __shared__ float sB[16][65];

    const int tid = threadIdx.x;
    const int m0 = blockIdx.y * 64;
    const int n0 = blockIdx.x * 64;
    const int ty = tid / 16, tx = tid % 16;

    const int lm  = tid >> 2;
    const int lk4 = tid & 3;
    const int lkB = tid >> 4;
    const int ln4 = tid & 15;

    float c[4][4] = {};

    for (int kb = 0; kb < D; kb += 16) {
        float4 av = *(const float4*)&g_ctx[(size_t)(m0 + lm) * D + kb + 4 * lk4];
        float4 wv = *(const float4*)&Wo[(size_t)(kb + lkB) * D + n0 + 4 * ln4];
        __syncthreads();
        sA[4*lk4+0][lm] = av.x; sA[4*lk4+1][lm] = av.y;
        sA[4*lk4+2][lm] = av.z; sA[4*lk4+3][lm] = av.w;
        sB[lkB][4*ln4+0] = wv.x; sB[lkB][4*ln4+1] = wv.y;
        sB[lkB][4*ln4+2] = wv.z; sB[lkB][4*ln4+3] = wv.w;
        __syncthreads();
        #pragma unroll
        for (int kk = 0; kk < 16; kk++) {
            float a[4], b_[4];
            #pragma unroll
            for (int i = 0; i < 4; i++) a[i]  = sA[kk][ty + 16*i];
            #pragma unroll
            for (int j = 0; j < 4; j++) b_[j] = sB[kk][tx + 16*j];
            #pragma unroll
            for (int i = 0; i < 4; i++)
                #pragma unroll
                for (int j = 0; j < 4; j++)
                    c[i][j] += a[i] * b_[j];
        }
    }

    #pragma unroll
    for (int i = 0; i < 4; i++)
        #pragma unroll
        for (int j = 0; j < 4; j++) {
            int m = m0 + ty + 16*i;
            int n = n0 + tx + 16*j;
            out[(size_t)m * D + n] = c[i][j] + bo[n];
        }
}

// ---------------------------------------------------------------------------
extern "C" void kernel_launch(void* const* d_in, const int* in_sizes, int n_in,
                              void* d_out, int out_size)
{
    const float* query = (const float*)d_in[0];
    const float* key   = (const float*)d_in[1];
    const float* value = (const float*)d_in[2];
    const float* Wq    = (const float*)d_in[3];
    const float* bq    = (const float*)d_in[4];
    const float* Wk    = (const float*)d_in[5];
    const float* bk    = (const float*)d_in[6];
    const float* Wv    = (const float*)d_in[7];
    const float* bv    = (const float*)d_in[8];
    const float* Wo    = (const float*)d_in[9];
    const float* bo    = (const float*)d_in[10];

    float* out  = (float*)d_out;                      // [B,S,D]
    float* attn = out + (size_t)MROWS * D;            // [B,H,S,S]

    cudaFuncSetAttribute(attn_kernel, cudaFuncAttributeMaxDynamicSharedMemorySize,
                         SMEM_ATTN_BYTES);

    qkv_kernel<<<dim3(D/64, MROWS/64, 3), 256>>>(query, key, value,
                                                 Wq, Wk, Wv, bq, bk, bv);
    attn_kernel<<<dim3(S/QT, BB*H), 256, SMEM_ATTN_BYTES>>>(attn);
    oproj_kernel<<<dim3(D/64, MROWS/64), 256>>>(Wo, bo, out);
}

// round 5
// speedup vs baseline: 1.2384x; 1.2304x over previous
#include <cuda_runtime.h>
#include <cuda_bf16.h>
#include <cstdint>

#define BB 2
#define S  2048
#define H  16
#define D  1024
#define DK 64
#define MROWS (BB*S)   // 4096

// ===================== warp-MMA helpers (sm_80+, valid on sm_103) =====================
#define LDSM4(r, a) asm volatile( \
    "ldmatrix.sync.aligned.m8n8.x4.shared.b16 {%0,%1,%2,%3}, [%4];" \
    : "=r"((r)[0]),"=r"((r)[1]),"=r"((r)[2]),"=r"((r)[3]) : "r"(a))
#define LDSM2(r, a) asm volatile( \
    "ldmatrix.sync.aligned.m8n8.x2.shared.b16 {%0,%1}, [%2];" \
    : "=r"((r)[0]),"=r"((r)[1]) : "r"(a))
#define MMA16816(c, a, b) asm volatile( \
    "mma.sync.aligned.m16n8k16.row.col.f32.bf16.bf16.f32 " \
    "{%0,%1,%2,%3}, {%4,%5,%6,%7}, {%8,%9}, {%0,%1,%2,%3};" \
    : "+f"((c)[0]),"+f"((c)[1]),"+f"((c)[2]),"+f"((c)[3]) \
    : "r"((a)[0]),"r"((a)[1]),"r"((a)[2]),"r"((a)[3]), "r"((b)[0]),"r"((b)[1]))

__device__ __forceinline__ uint32_t smem_u32(const void* p) {
    uint32_t a;
    asm("{ .reg .u64 t; cvta.to.shared.u64 t, %1; cvt.u32.u64 %0, t; }" : "=r"(a) : "l"(p));
    return a;
}

// FFMA-pipe exp (avoids MUFU.EX2 rt=8 wall); rel err ~2e-6 for x<=0
__device__ __forceinline__ float fexp(float x) {
    x = fmaxf(x, -87.0f);
    float y = x * 1.44269504088896341f;
    float t = y + 12582912.0f;
    int ni = __float_as_int(t) - 0x4B400000;
    float f = y - (t - 12582912.0f);
    float p = 1.33335581464284430e-3f;
    p = fmaf(p, f, 9.61812910762847716e-3f);
    p = fmaf(p, f, 5.55041086648215800e-2f);
    p = fmaf(p, f, 2.40226506959100712e-1f);
    p = fmaf(p, f, 6.93147180559945309e-1f);
    p = fmaf(p, f, 1.0f);
    return p * __int_as_float((ni + 127) << 23);
}

// ===================== device-global scratch (16B aligned for vector casts) ============
__device__ __align__(16) __nv_bfloat16 g_Xhi [3u*MROWS*D];
__device__ __align__(16) __nv_bfloat16 g_Xmid[3u*MROWS*D];
__device__ __align__(16) __nv_bfloat16 g_WhiT [4u*D*D];   // [z][n][k] transposed
__device__ __align__(16) __nv_bfloat16 g_WmidT[4u*D*D];
__device__ __align__(16) float g_Q[BB*H*S*DK];
__device__ __align__(16) float g_K[BB*H*S*DK];
__device__ __align__(16) float g_V[BB*H*S*DK];
__device__ __align__(16) __nv_bfloat16 g_ctx_hi [MROWS*D];
__device__ __align__(16) __nv_bfloat16 g_ctx_mid[MROWS*D];

// ===================== prep: split activations =====================
__global__ __launch_bounds__(256) void conv_acts(
    const float* __restrict__ q, const float* __restrict__ k, const float* __restrict__ v)
{
    const size_t per4 = (size_t)MROWS * D / 4;
    size_t i = (size_t)blockIdx.x * 256 + threadIdx.x;
    int z = (int)(i / per4);
    size_t r = i - (size_t)z * per4;
    const float* src = (z == 0) ? q : (z == 1) ? k : v;
    float4 x = ((const float4*)src)[r];
    __nv_bfloat16 h0 = __float2bfloat16(x.x), h1 = __float2bfloat16(x.y);
    __nv_bfloat16 h2 = __float2bfloat16(x.z), h3 = __float2bfloat16(x.w);
    size_t o = i * 4;
    ((__nv_bfloat162*)(g_Xhi + o))[0] = __halves2bfloat162(h0, h1);
    ((__nv_bfloat162*)(g_Xhi + o))[1] = __halves2bfloat162(h2, h3);
    ((__nv_bfloat162*)(g_Xmid + o))[0] = __halves2bfloat162(
        __float2bfloat16(x.x - __bfloat162float(h0)), __float2bfloat16(x.y - __bfloat162float(h1)));
    ((__nv_bfloat162*)(g_Xmid + o))[1] = __halves2bfloat162(
        __float2bfloat16(x.z - __bfloat162float(h2)), __float2bfloat16(x.w - __bfloat162float(h3)));
}

// ===================== prep: split + transpose weights =====================
__global__ __launch_bounds__(256) void conv_W(
    const float* __restrict__ Wq, const float* __restrict__ Wk,
    const float* __restrict__ Wv, const float* __restrict__ Wo)
{
    __shared__ __nv_bfloat16 th[64][68];
    __shared__ __nv_bfloat16 tm[64][68];
    const int z = blockIdx.z;
    const float* src = (z == 0) ? Wq : (z == 1) ? Wk : (z == 2) ? Wv : Wo;
    const int k0 = blockIdx.y * 64, n0 = blockIdx.x * 64;
    const int t = threadIdx.x;
    #pragma unroll
    for (int p = 0; p < 4; p++) {
        int r = p * 16 + (t >> 4);
        int c4 = (t & 15) * 4;
        float4 w = *(const float4*)&src[(size_t)(k0 + r) * D + n0 + c4];
        float vv[4] = {w.x, w.y, w.z, w.w};
        #pragma unroll
        for (int j = 0; j < 4; j++) {
            __nv_bfloat16 hh = __float2bfloat16(vv[j]);
            th[c4 + j][r] = hh;
            tm[c4 + j][r] = __float2bfloat16(vv[j] - __bfloat162float(hh));
        }
    }
    __syncthreads();
    #pragma unroll
    for (int p = 0; p < 4; p++) {
        int n = p * 16 + (t >> 4);
        int k4 = (t & 15) * 4;
        size_t o = (size_t)z * D * D + (size_t)(n0 + n) * D + k0 + k4;
        *(uint2*)&g_WhiT[o]  = *(const uint2*)&th[n][k4];
        *(uint2*)&g_WmidT[o] = *(const uint2*)&tm[n][k4];
    }
}

// ===================== HMMA GEMM mainloop (128x128 CTA tile, K=1024) =====================
// smem row stride 144 B (16B-aligned rows -> legal ldmatrix; 144%128=16 -> conflict-free LDSM)
#define LDA 144
#define TILE_B (128*LDA)     // 18432
#define OFF_AM TILE_B
#define OFF_BH (2*TILE_B)
#define OFF_BM (3*TILE_B)
#define GEMM_SMEM (4*TILE_B) // 73728

__device__ __forceinline__ void hgemm_main(
    const __nv_bfloat16* __restrict__ Ah, const __nv_bfloat16* __restrict__ Am,
    const __nv_bfloat16* __restrict__ Bh, const __nv_bfloat16* __restrict__ Bm,
    char* smem, float acc[4][4][4])
{
    const int tid = threadIdx.x, lane = tid & 31, wid = tid >> 5;
    const int wm = wid >> 2, wn = wid & 3;
    const uint32_t sb = smem_u32(smem);

    const uint32_t a_row = (uint32_t)(wm * 64 + (lane & 15)) * LDA + (lane >> 4) * 16;
    const uint32_t b_row = (uint32_t)(wn * 32 + (lane & 7)) * LDA + ((lane >> 3) & 1) * 16;

    for (int ch = 0; ch < 16; ch++) {
        const int kb = ch * 64;
        #pragma unroll
        for (int p = 0; p < 8; p++) {
            int idx = p * 256 + tid;
            int row = idx >> 4, cg = idx & 15;
            size_t g = (size_t)row * D + kb + cg * 4;
            int so = row * LDA + cg * 8;
            *(uint2*)(smem + so)          = *(const uint2*)(Ah + g);
            *(uint2*)(smem + OFF_AM + so) = *(const uint2*)(Am + g);
            *(uint2*)(smem + OFF_BH + so) = *(const uint2*)(Bh + g);
            *(uint2*)(smem + OFF_BM + so) = *(const uint2*)(Bm + g);
        }
        __syncthreads();

        #pragma unroll
        for (int ks = 0; ks < 4; ks++) {
            uint32_t ah[4][4], am[4][4], bh[4][2], bm[4][2];
            #pragma unroll
            for (int mt = 0; mt < 4; mt++) {
                uint32_t ra = sb + a_row + mt * (16 * LDA) + ks * 32;
                LDSM4(ah[mt], ra);
                LDSM4(am[mt], ra + OFF_AM);
            }
            #pragma unroll
            for (int nt = 0; nt < 4; nt++) {
                uint32_t rb = sb + OFF_BH + b_row + nt * (8 * LDA) + ks * 32;
                LDSM2(bh[nt], rb);
                LDSM2(bm[nt], rb + (OFF_BM - OFF_BH));
            }
            #pragma unroll
            for (int mt = 0; mt < 4; mt++)
                #pragma unroll
                for (int nt = 0; nt < 4; nt++) {
                    MMA16816(acc[mt][nt], ah[mt], bh[nt]);
                    MMA16816(acc[mt][nt], ah[mt], bm[nt]);
                    MMA16816(acc[mt][nt], am[mt], bh[nt]);
                }
        }
        __syncthreads();
    }
}

// ===================== QKV GEMM (head-major scatter epilogue) =====================
__global__ __launch_bounds__(256) void qkv_mm(
    const float* __restrict__ bq, const float* __restrict__ bk, const float* __restrict__ bv)
{
    extern __shared__ char smem[];
    const int z = blockIdx.z, m0 = blockIdx.y * 128, n0 = blockIdx.x * 128;
    float acc[4][4][4] = {};
    hgemm_main(g_Xhi + ((size_t)z * MROWS + m0) * D, g_Xmid + ((size_t)z * MROWS + m0) * D,
               g_WhiT + ((size_t)z * D + n0) * D,    g_WmidT + ((size_t)z * D + n0) * D,
               smem, acc);

    const float* bias = (z == 0) ? bq : (z == 1) ? bk : bv;
    float* outp       = (z == 0) ? g_Q : (z == 1) ? g_K : g_V;
    const int tid = threadIdx.x, lane = tid & 31, wid = tid >> 5;
    const int wm = wid >> 2, wn = wid & 3;
    const int g2 = lane >> 2, t4 = lane & 3;

    #pragma unroll
    for (int nt = 0; nt < 4; nt++) {
        const int c = n0 + wn * 32 + nt * 8 + 2 * t4;
        const float b0v = __ldg(&bias[c]), b1v = __ldg(&bias[c + 1]);
        const int h = c >> 6, d = c & 63;
        #pragma unroll
        for (int mt = 0; mt < 4; mt++) {
            int r0 = m0 + wm * 64 + mt * 16 + g2;
            int b = r0 >> 11, s = r0 & (S - 1);
            float* p0 = outp + (((size_t)(b * H + h) * S + s) * DK + d);
            *(float2*)p0 = make_float2(acc[mt][nt][0] + b0v, acc[mt][nt][1] + b1v);
            float* p1 = p0 + 8 * DK;   // row +8 within same 128-row tile -> same b
            *(float2*)p1 = make_float2(acc[mt][nt][2] + b0v, acc[mt][nt][3] + b1v);
        }
    }
}

// ===================== O-proj GEMM (row-major epilogue) =====================
__global__ __launch_bounds__(256) void o_mm(const float* __restrict__ bo, float* __restrict__ out)
{
    extern __shared__ char smem[];
    const int m0 = blockIdx.y * 128, n0 = blockIdx.x * 128;
    float acc[4][4][4] = {};
    hgemm_main(g_ctx_hi + (size_t)m0 * D, g_ctx_mid + (size_t)m0 * D,
               g_WhiT + ((size_t)3 * D + n0) * D, g_WmidT + ((size_t)3 * D + n0) * D,
               smem, acc);

    const int tid = threadIdx.x, lane = tid & 31, wid = tid >> 5;
    const int wm = wid >> 2, wn = wid & 3;
    const int g2 = lane >> 2, t4 = lane & 3;

    #pragma unroll
    for (int nt = 0; nt < 4; nt++) {
        const int c = n0 + wn * 32 + nt * 8 + 2 * t4;
        const float b0v = __ldg(&bo[c]), b1v = __ldg(&bo[c + 1]);
        #pragma unroll
        for (int mt = 0; mt < 4; mt++) {
            int r0 = m0 + wm * 64 + mt * 16 + g2;
            float* p0 = out + (size_t)r0 * D + c;
            *(float2*)p0 = make_float2(acc[mt][nt][0] + b0v, acc[mt][nt][1] + b1v);
            float* p1 = p0 + 8 * D;
            *(float2*)p1 = make_float2(acc[mt][nt][2] + b0v, acc[mt][nt][3] + b1v);
        }
    }
}

// ===================== attention (scalar fp32, poly-exp) =====================
#define QT 16
#define KT 256
#define SMEM_ATTN_BYTES ((QT*S + KT*65 + QT*DK) * 4)

__global__ __launch_bounds__(256) void attn_kernel(float* __restrict__ attn_out)
{
    extern __shared__ float sm[];
    float* sS = sm;
    float* sK = sm + QT * S;
    float* sQ = sK + KT * 65;

    const int tid = threadIdx.x;
    const int bh = blockIdx.y;
    const int q0 = blockIdx.x * QT;
    const float* Qp = g_Q + ((size_t)bh * S + q0) * DK;
    const float* Kp = g_K + (size_t)bh * S * DK;
    const float* Vp = g_V + (size_t)bh * S * DK;

    { int qi = tid >> 4, d4 = tid & 15;
      *(float4*)&sQ[qi * DK + 4 * d4] = *(const float4*)&Qp[qi * DK + 4 * d4]; }

    const int l = tid & 63, qg = tid >> 6;
    const float scale = 0.125f;

    for (int kt = 0; kt < S; kt += KT) {
        #pragma unroll
        for (int r = 0; r < 16; r++) {
            int row = r * 16 + (tid >> 4), d4 = tid & 15;
            float4 v = *(const float4*)&Kp[(size_t)(kt + row) * DK + 4 * d4];
            sK[row * 65 + 4*d4 + 0] = v.x; sK[row * 65 + 4*d4 + 1] = v.y;
            sK[row * 65 + 4*d4 + 2] = v.z; sK[row * 65 + 4*d4 + 3] = v.w;
        }
        __syncthreads();
        float acc[4][4] = {};
        #pragma unroll 8
        for (int d = 0; d < DK; d++) {
            float kv[4], qv[4];
            #pragma unroll
            for (int j = 0; j < 4; j++) kv[j] = sK[(l + 64*j) * 65 + d];
            #pragma unroll
            for (int i = 0; i < 4; i++) qv[i] = sQ[(qg*4 + i) * DK + d];
            #pragma unroll
            for (int i = 0; i < 4; i++)
                #pragma unroll
                for (int j = 0; j < 4; j++) acc[i][j] += qv[i] * kv[j];
        }
        #pragma unroll
        for (int i = 0; i < 4; i++)
            #pragma unroll
            for (int j = 0; j < 4; j++)
                sS[(qg*4 + i) * S + kt + l + 64*j] = acc[i][j] * scale;
        __syncthreads();
    }

    { int w = tid >> 5, lane = tid & 31;
      #pragma unroll
      for (int rr = 0; rr < 2; rr++) {
        int r = w * 2 + rr;
        float* row = sS + r * S;
        float mx = -1e30f;
        for (int c2 = lane; c2 < S; c2 += 32) mx = fmaxf(mx, row[c2]);
        #pragma unroll
        for (int o = 16; o; o >>= 1) mx = fmaxf(mx, __shfl_xor_sync(0xffffffffu, mx, o));
        float sum = 0.f;
        for (int c2 = lane; c2 < S; c2 += 32) {
            float p = fexp(row[c2] - mx);
            row[c2] = p; sum += p;
        }
        #pragma unroll
        for (int o = 16; o; o >>= 1) sum += __shfl_xor_sync(0xffffffffu, sum, o);
        float inv = 1.0f / sum;
        float* arow = attn_out + ((size_t)bh * S + q0 + r) * S;
        for (int c2 = lane; c2 < S; c2 += 32) {
            float p = row[c2] * inv;
            row[c2] = p; arow[c2] = p;
        }
      }
    }
    __syncthreads();

    const int t = tid & 63, grp = tid >> 6;
    const int dj = t & 15, qb = t >> 4;
    float acc2[4][4] = {};
    for (int vt = 0; vt < S; vt += KT) {
        #pragma unroll
        for (int r = 0; r < 16; r++) {
            int row = r * 16 + (tid >> 4), d4 = tid & 15;
            float4 v = *(const float4*)&Vp[(size_t)(vt + row) * DK + 4 * d4];
            sK[row * 65 + 4*d4 + 0] = v.x; sK[row * 65 + 4*d4 + 1] = v.y;
            sK[row * 65 + 4*d4 + 2] = v.z; sK[row * 65 + 4*d4 + 3] = v.w;
        }
        __syncthreads();
        int kbase = vt + grp * 64;
        #pragma unroll 8
        for (int kk = 0; kk < 64; kk++) {
            float pv[4], vv[4];
            #pragma unroll
            for (int i = 0; i < 4; i++) pv[i] = sS[(qb + 4*i) * S + kbase + kk];
            #pragma unroll
            for (int j = 0; j < 4; j++) vv[j] = sK[(grp*64 + kk) * 65 + dj + 16*j];
            #pragma unroll
            for (int i = 0; i < 4; i++)
                #pragma unroll
                for (int j = 0; j < 4; j++) acc2[i][j] += pv[i] * vv[j];
        }
        __syncthreads();
    }

    float* red = sK;
    #pragma unroll
    for (int i = 0; i < 4; i++)
        #pragma unroll
        for (int j = 0; j < 4; j++)
            red[grp * (QT*DK) + (qb + 4*i) * DK + dj + 16*j] = acc2[i][j];
    __syncthreads();

    const int b = bh >> 4, h = bh & 15;
    for (int e = tid; e < QT * DK; e += 256) {
        float v = red[e] + red[QT*DK + e] + red[2*QT*DK + e] + red[3*QT*DK + e];
        int qi = e >> 6, d = e & 63;
        size_t idx = ((size_t)(b * S) + q0 + qi) * D + h * DK + d;
        __nv_bfloat16 hi = __float2bfloat16(v);
        g_ctx_hi[idx] = hi;
        g_ctx_mid[idx] = __float2bfloat16(v - __bfloat162float(hi));
    }
}

// ===================== launch =====================
extern "C" void kernel_launch(void* const* d_in, const int* in_sizes, int n_in,
                              void* d_out, int out_size)
{
    const float* query = (const float*)d_in[0];
    const float* key   = (const float*)d_in[1];
    const float* value = (const float*)d_in[2];
    const float* Wq = (const float*)d_in[3];
    const float* bq = (const float*)d_in[4];
    const float* Wk = (const float*)d_in[5];
    const float* bk = (const float*)d_in[6];
    const float* Wv = (const float*)d_in[7];
    const float* bv = (const float*)d_in[8];
    const float* Wo = (const float*)d_in[9];
    const float* bo = (const float*)d_in[10];

    float* out  = (float*)d_out;
    float* attn = out + (size_t)MROWS * D;

    cudaFuncSetAttribute(attn_kernel, cudaFuncAttributeMaxDynamicSharedMemorySize, SMEM_ATTN_BYTES);
    cudaFuncSetAttribute(qkv_mm, cudaFuncAttributeMaxDynamicSharedMemorySize, GEMM_SMEM);
    cudaFuncSetAttribute(o_mm, cudaFuncAttributeMaxDynamicSharedMemorySize, GEMM_SMEM);

    conv_acts<<<3 * MROWS * D / 4 / 256, 256>>>(query, key, value);
    conv_W<<<dim3(16, 16, 4), 256>>>(Wq, Wk, Wv, Wo);
    qkv_mm<<<dim3(8, 32, 3), 256, GEMM_SMEM>>>(bq, bk, bv);
    attn_kernel<<<dim3(S / QT, BB * H), 256, SMEM_ATTN_BYTES>>>(attn);
    o_mm<<<dim3(8, 32), 256, GEMM_SMEM>>>(bo, out);
}

// round 6
// speedup vs baseline: 1.6767x; 1.3539x over previous
#include <cuda_runtime.h>
#include <cuda_bf16.h>
#include <cstdint>

#define BB 2
#define S  2048
#define H  16
#define D  1024
#define DK 64
#define MROWS (BB*S)   // 4096

// ===================== warp-MMA helpers (sm_80+, valid on sm_103) =====================
#define LDSM4(r, a) asm volatile( \
    "ldmatrix.sync.aligned.m8n8.x4.shared.b16 {%0,%1,%2,%3}, [%4];" \
    : "=r"((r)[0]),"=r"((r)[1]),"=r"((r)[2]),"=r"((r)[3]) : "r"(a))
#define LDSM2(r, a) asm volatile( \
    "ldmatrix.sync.aligned.m8n8.x2.shared.b16 {%0,%1}, [%2];" \
    : "=r"((r)[0]),"=r"((r)[1]) : "r"(a))
#define LDSM2T(r, a) asm volatile( \
    "ldmatrix.sync.aligned.m8n8.x2.trans.shared.b16 {%0,%1}, [%2];" \
    : "=r"((r)[0]),"=r"((r)[1]) : "r"(a))
#define MMA16816(c, a, b) asm volatile( \
    "mma.sync.aligned.m16n8k16.row.col.f32.bf16.bf16.f32 " \
    "{%0,%1,%2,%3}, {%4,%5,%6,%7}, {%8,%9}, {%0,%1,%2,%3};" \
    : "+f"((c)[0]),"+f"((c)[1]),"+f"((c)[2]),"+f"((c)[3]) \
    : "r"((a)[0]),"r"((a)[1]),"r"((a)[2]),"r"((a)[3]), "r"((b)[0]),"r"((b)[1]))

__device__ __forceinline__ uint32_t smem_u32(const void* p) {
    uint32_t a;
    asm("{ .reg .u64 t; cvta.to.shared.u64 t, %1; cvt.u32.u64 %0, t; }" : "=r"(a) : "l"(p));
    return a;
}

// FFMA-pipe exp; rel err ~2e-6 for x<=0
__device__ __forceinline__ float fexp(float x) {
    x = fmaxf(x, -87.0f);
    float y = x * 1.44269504088896341f;
    float t = y + 12582912.0f;
    int ni = __float_as_int(t) - 0x4B400000;
    float f = y - (t - 12582912.0f);
    float p = 1.33335581464284430e-3f;
    p = fmaf(p, f, 9.61812910762847716e-3f);
    p = fmaf(p, f, 5.55041086648215800e-2f);
    p = fmaf(p, f, 2.40226506959100712e-1f);
    p = fmaf(p, f, 6.93147180559945309e-1f);
    p = fmaf(p, f, 1.0f);
    return p * __int_as_float((ni + 127) << 23);
}

// ===================== device-global scratch (16B aligned) =====================
__device__ __align__(16) __nv_bfloat16 g_Xhi [3u*MROWS*D];
__device__ __align__(16) __nv_bfloat16 g_Xmid[3u*MROWS*D];
__device__ __align__(16) __nv_bfloat16 g_WhiT [4u*D*D];   // [z][n][k] transposed
__device__ __align__(16) __nv_bfloat16 g_WmidT[4u*D*D];
// Q/K/V head-major [B,H,S,DK], split bf16
__device__ __align__(16) __nv_bfloat16 g_Qh[BB*H*S*DK];
__device__ __align__(16) __nv_bfloat16 g_Qm[BB*H*S*DK];
__device__ __align__(16) __nv_bfloat16 g_Kh[BB*H*S*DK];
__device__ __align__(16) __nv_bfloat16 g_Km[BB*H*S*DK];
__device__ __align__(16) __nv_bfloat16 g_Vh[BB*H*S*DK];
__device__ __align__(16) __nv_bfloat16 g_Vm[BB*H*S*DK];
__device__ __align__(16) __nv_bfloat16 g_ctx_hi [MROWS*D];
__device__ __align__(16) __nv_bfloat16 g_ctx_mid[MROWS*D];

// ===================== prep: split activations =====================
__global__ __launch_bounds__(256) void conv_acts(
    const float* __restrict__ q, const float* __restrict__ k, const float* __restrict__ v)
{
    const size_t per4 = (size_t)MROWS * D / 4;
    size_t i = (size_t)blockIdx.x * 256 + threadIdx.x;
    int z = (int)(i / per4);
    size_t r = i - (size_t)z * per4;
    const float* src = (z == 0) ? q : (z == 1) ? k : v;
    float4 x = ((const float4*)src)[r];
    __nv_bfloat16 h0 = __float2bfloat16(x.x), h1 = __float2bfloat16(x.y);
    __nv_bfloat16 h2 = __float2bfloat16(x.z), h3 = __float2bfloat16(x.w);
    size_t o = i * 4;
    ((__nv_bfloat162*)(g_Xhi + o))[0] = __halves2bfloat162(h0, h1);
    ((__nv_bfloat162*)(g_Xhi + o))[1] = __halves2bfloat162(h2, h3);
    ((__nv_bfloat162*)(g_Xmid + o))[0] = __halves2bfloat162(
        __float2bfloat16(x.x - __bfloat162float(h0)), __float2bfloat16(x.y - __bfloat162float(h1)));
    ((__nv_bfloat162*)(g_Xmid + o))[1] = __halves2bfloat162(
        __float2bfloat16(x.z - __bfloat162float(h2)), __float2bfloat16(x.w - __bfloat162float(h3)));
}

// ===================== prep: split + transpose weights =====================
__global__ __launch_bounds__(256) void conv_W(
    const float* __restrict__ Wq, const float* __restrict__ Wk,
    const float* __restrict__ Wv, const float* __restrict__ Wo)
{
    __shared__ __nv_bfloat16 th[64][68];
    __shared__ __nv_bfloat16 tm[64][68];
    const int z = blockIdx.z;
    const float* src = (z == 0) ? Wq : (z == 1) ? Wk : (z == 2) ? Wv : Wo;
    const int k0 = blockIdx.y * 64, n0 = blockIdx.x * 64;
    const int t = threadIdx.x;
    #pragma unroll
    for (int p = 0; p < 4; p++) {
        int r = p * 16 + (t >> 4);
        int c4 = (t & 15) * 4;
        float4 w = *(const float4*)&src[(size_t)(k0 + r) * D + n0 + c4];
        float vv[4] = {w.x, w.y, w.z, w.w};
        #pragma unroll
        for (int j = 0; j < 4; j++) {
            __nv_bfloat16 hh = __float2bfloat16(vv[j]);
            th[c4 + j][r] = hh;
            tm[c4 + j][r] = __float2bfloat16(vv[j] - __bfloat162float(hh));
        }
    }
    __syncthreads();
    #pragma unroll
    for (int p = 0; p < 4; p++) {
        int n = p * 16 + (t >> 4);
        int k4 = (t & 15) * 4;
        size_t o = (size_t)z * D * D + (size_t)(n0 + n) * D + k0 + k4;
        *(uint2*)&g_WhiT[o]  = *(const uint2*)&th[n][k4];
        *(uint2*)&g_WmidT[o] = *(const uint2*)&tm[n][k4];
    }
}

// ===================== HMMA GEMM mainloop (128x128 CTA tile, K=1024) =====================
#define LDA 144
#define TILE_B (128*LDA)     // 18432
#define OFF_AM TILE_B
#define OFF_BH (2*TILE_B)
#define OFF_BM (3*TILE_B)
#define GEMM_SMEM (4*TILE_B) // 73728

__device__ __forceinline__ void hgemm_main(
    const __nv_bfloat16* __restrict__ Ah, const __nv_bfloat16* __restrict__ Am,
    const __nv_bfloat16* __restrict__ Bh, const __nv_bfloat16* __restrict__ Bm,
    char* smem, float acc[4][4][4])
{
    const int tid = threadIdx.x, lane = tid & 31, wid = tid >> 5;
    const int wm = wid >> 2, wn = wid & 3;
    const uint32_t sb = smem_u32(smem);

    const uint32_t a_row = (uint32_t)(wm * 64 + (lane & 15)) * LDA + (lane >> 4) * 16;
    const uint32_t b_row = (uint32_t)(wn * 32 + (lane & 7)) * LDA + ((lane >> 3) & 1) * 16;

    for (int ch = 0; ch < 16; ch++) {
        const int kb = ch * 64;
        #pragma unroll
        for (int p = 0; p < 8; p++) {
            int idx = p * 256 + tid;
            int row = idx >> 4, cg = idx & 15;
            size_t g = (size_t)row * D + kb + cg * 4;
            int so = row * LDA + cg * 8;
            *(uint2*)(smem + so)          = *(const uint2*)(Ah + g);
            *(uint2*)(smem + OFF_AM + so) = *(const uint2*)(Am + g);
            *(uint2*)(smem + OFF_BH + so) = *(const uint2*)(Bh + g);
            *(uint2*)(smem + OFF_BM + so) = *(const uint2*)(Bm + g);
        }
        __syncthreads();

        #pragma unroll
        for (int ks = 0; ks < 4; ks++) {
            uint32_t ah[4][4], am[4][4], bh[4][2], bm[4][2];
            #pragma unroll
            for (int mt = 0; mt < 4; mt++) {
                uint32_t ra = sb + a_row + mt * (16 * LDA) + ks * 32;
                LDSM4(ah[mt], ra);
                LDSM4(am[mt], ra + OFF_AM);
            }
            #pragma unroll
            for (int nt = 0; nt < 4; nt++) {
                uint32_t rb = sb + OFF_BH + b_row + nt * (8 * LDA) + ks * 32;
                LDSM2(bh[nt], rb);
                LDSM2(bm[nt], rb + (OFF_BM - OFF_BH));
            }
            #pragma unroll
            for (int mt = 0; mt < 4; mt++)
                #pragma unroll
                for (int nt = 0; nt < 4; nt++) {
                    MMA16816(acc[mt][nt], ah[mt], bh[nt]);
                    MMA16816(acc[mt][nt], ah[mt], bm[nt]);
                    MMA16816(acc[mt][nt], am[mt], bh[nt]);
                }
        }
        __syncthreads();
    }
}

// ===================== QKV GEMM: epilogue writes split bf16 head-major =====================
__global__ __launch_bounds__(256) void qkv_mm(
    const float* __restrict__ bq, const float* __restrict__ bk, const float* __restrict__ bv)
{
    extern __shared__ char smem[];
    const int z = blockIdx.z, m0 = blockIdx.y * 128, n0 = blockIdx.x * 128;
    float acc[4][4][4] = {};
    hgemm_main(g_Xhi + ((size_t)z * MROWS + m0) * D, g_Xmid + ((size_t)z * MROWS + m0) * D,
               g_WhiT + ((size_t)z * D + n0) * D,    g_WmidT + ((size_t)z * D + n0) * D,
               smem, acc);

    const float* bias = (z == 0) ? bq : (z == 1) ? bk : bv;
    __nv_bfloat16* outh = (z == 0) ? g_Qh : (z == 1) ? g_Kh : g_Vh;
    __nv_bfloat16* outm = (z == 0) ? g_Qm : (z == 1) ? g_Km : g_Vm;
    const int tid = threadIdx.x, lane = tid & 31, wid = tid >> 5;
    const int wm = wid >> 2, wn = wid & 3;
    const int g2 = lane >> 2, t4 = lane & 3;

    #pragma unroll
    for (int nt = 0; nt < 4; nt++) {
        const int c = n0 + wn * 32 + nt * 8 + 2 * t4;
        const float b0v = __ldg(&bias[c]), b1v = __ldg(&bias[c + 1]);
        const int h = c >> 6, d = c & 63;
        #pragma unroll
        for (int mt = 0; mt < 4; mt++) {
            int r0 = m0 + wm * 64 + mt * 16 + g2;
            int b = r0 >> 11, s = r0 & (S - 1);
            size_t base = ((size_t)(b * H + h) * S + s) * DK + d;
            #pragma unroll
            for (int hp = 0; hp < 2; hp++) {   // row r0 then r0+8
                float v0 = acc[mt][nt][2*hp + 0] + b0v;
                float v1 = acc[mt][nt][2*hp + 1] + b1v;
                __nv_bfloat16 h0 = __float2bfloat16(v0), h1 = __float2bfloat16(v1);
                size_t o = base + (size_t)hp * 8 * DK;
                *(__nv_bfloat162*)(outh + o) = __halves2bfloat162(h0, h1);
                *(__nv_bfloat162*)(outm + o) = __halves2bfloat162(
                    __float2bfloat16(v0 - __bfloat162float(h0)),
                    __float2bfloat16(v1 - __bfloat162float(h1)));
            }
        }
    }
}

// ===================== O-proj GEMM (row-major epilogue) =====================
__global__ __launch_bounds__(256) void o_mm(const float* __restrict__ bo, float* __restrict__ out)
{
    extern __shared__ char smem[];
    const int m0 = blockIdx.y * 128, n0 = blockIdx.x * 128;
    float acc[4][4][4] = {};
    hgemm_main(g_ctx_hi + (size_t)m0 * D, g_ctx_mid + (size_t)m0 * D,
               g_WhiT + ((size_t)3 * D + n0) * D, g_WmidT + ((size_t)3 * D + n0) * D,
               smem, acc);

    const int tid = threadIdx.x, lane = tid & 31, wid = tid >> 5;
    const int wm = wid >> 2, wn = wid & 3;
    const int g2 = lane >> 2, t4 = lane & 3;

    #pragma unroll
    for (int nt = 0; nt < 4; nt++) {
        const int c = n0 + wn * 32 + nt * 8 + 2 * t4;
        const float b0v = __ldg(&bo[c]), b1v = __ldg(&bo[c + 1]);
        #pragma unroll
        for (int mt = 0; mt < 4; mt++) {
            int r0 = m0 + wm * 64 + mt * 16 + g2;
            float* p0 = out + (size_t)r0 * D + c;
            *(float2*)p0 = make_float2(acc[mt][nt][0] + b0v, acc[mt][nt][1] + b1v);
            float* p1 = p0 + 8 * D;
            *(float2*)p1 = make_float2(acc[mt][nt][2] + b0v, acc[mt][nt][3] + b1v);
        }
    }
}

// ===================== attention: HMMA QK^T + softmax + HMMA PV =====================
// smem layout (bytes):
//   sS   @0       : 16*2048*4 = 131072 (fp32 score strip)
//   sKVh @131072  : 256*144   = 36864  (K or V tile, hi split)
//   sKVm @167936  : 36864
//   sQh  @204800  : 16*144    = 2304
//   sQm  @207104  : 2304
//   sPh  @209408  : 16*528    = 8448   (P tile, bf16, row stride 528)
//   sPm  @217856  : 8448
#define ATT_SS   0
#define ATT_KVH  131072
#define ATT_KVM  167936
#define ATT_QH   204800
#define ATT_QM   207104
#define ATT_PH   209408
#define ATT_PM   217856
#define SMEM_ATTN_BYTES 226304
#define QT 16
#define KT 256
#define LDP 528

__global__ __launch_bounds__(256) void attn_kernel(float* __restrict__ attn_out)
{
    extern __shared__ char sm[];
    float* sS = (float*)sm;
    const uint32_t sb = smem_u32(sm);

    const int tid = threadIdx.x, lane = tid & 31, wid = tid >> 5;
    const int bh = blockIdx.y;
    const int q0 = blockIdx.x * QT;

    const __nv_bfloat16* Qh = g_Qh + ((size_t)bh * S + q0) * DK;
    const __nv_bfloat16* Qm = g_Qm + ((size_t)bh * S + q0) * DK;
    const __nv_bfloat16* Kh = g_Kh + (size_t)bh * S * DK;
    const __nv_bfloat16* Km = g_Km + (size_t)bh * S * DK;
    const __nv_bfloat16* Vh = g_Vh + (size_t)bh * S * DK;
    const __nv_bfloat16* Vm = g_Vm + (size_t)bh * S * DK;

    // load Q tile (both splits): 16 rows x 64 bf16, row stride 144
    {
        int qi = tid >> 4, c = tid & 15;
        *(uint2*)(sm + ATT_QH + qi * 144 + c * 8) = *(const uint2*)(Qh + qi * DK + c * 4);
        *(uint2*)(sm + ATT_QM + qi * 144 + c * 8) = *(const uint2*)(Qm + qi * DK + c * 4);
    }

    // ---- Phase 1: scores via HMMA (3-term split) ----
    const uint32_t aQh = sb + ATT_QH + (lane & 15) * 144 + (lane >> 4) * 16;
    const uint32_t aQm = sb + ATT_QM + (lane & 15) * 144 + (lane >> 4) * 16;
    const uint32_t bK  = sb + ATT_KVH + (uint32_t)(wid * 32 + (lane & 7)) * 144 + ((lane >> 3) & 1) * 16;

    for (int kt = 0; kt < S; kt += KT) {
        #pragma unroll
        for (int r = 0; r < 16; r++) {
            int row = r * 16 + (tid >> 4), c = tid & 15;
            size_t g = (size_t)(kt + row) * DK + c * 4;
            *(uint2*)(sm + ATT_KVH + row * 144 + c * 8) = *(const uint2*)(Kh + g);
            *(uint2*)(sm + ATT_KVM + row * 144 + c * 8) = *(const uint2*)(Km + g);
        }
        __syncthreads();

        float acc[4][4] = {};
        #pragma unroll
        for (int ks = 0; ks < 4; ks++) {
            uint32_t ah[4], am[4], kbh[4][2], kbm[4][2];
            LDSM4(ah, aQh + ks * 32);
            LDSM4(am, aQm + ks * 32);
            #pragma unroll
            for (int nt = 0; nt < 4; nt++) {
                uint32_t rb = bK + nt * (8 * 144) + ks * 32;
                LDSM2(kbh[nt], rb);
                LDSM2(kbm[nt], rb + (ATT_KVM - ATT_KVH));
                MMA16816(acc[nt], ah, kbh[nt]);
                MMA16816(acc[nt], ah, kbm[nt]);
                MMA16816(acc[nt], am, kbh[nt]);
            }
        }
        // store scores * 0.125 into sS
        {
            int r = lane >> 2;
            int cbase = kt + wid * 32 + (lane & 3) * 2;
            #pragma unroll
            for (int nt = 0; nt < 4; nt++) {
                int c = cbase + nt * 8;
                *(float2*)&sS[r * S + c] =
                    make_float2(acc[nt][0] * 0.125f, acc[nt][1] * 0.125f);
                *(float2*)&sS[(r + 8) * S + c] =
                    make_float2(acc[nt][2] * 0.125f, acc[nt][3] * 0.125f);
            }
        }
        __syncthreads();
    }

    // ---- Phase 2: softmax in place + single attn write ----
    {
        int w = wid, ln = lane;
        #pragma unroll
        for (int rr = 0; rr < 2; rr++) {
            int r = w * 2 + rr;
            float* row = sS + r * S;
            float mx = -1e30f;
            for (int c2 = ln; c2 < S; c2 += 32) mx = fmaxf(mx, row[c2]);
            #pragma unroll
            for (int o = 16; o; o >>= 1) mx = fmaxf(mx, __shfl_xor_sync(0xffffffffu, mx, o));
            float sum = 0.f;
            for (int c2 = ln; c2 < S; c2 += 32) {
                float p = fexp(row[c2] - mx);
                row[c2] = p; sum += p;
            }
            #pragma unroll
            for (int o = 16; o; o >>= 1) sum += __shfl_xor_sync(0xffffffffu, sum, o);
            float inv = 1.0f / sum;
            float* arow = attn_out + ((size_t)bh * S + q0 + r) * S;
            for (int c2 = ln; c2 < S; c2 += 32) {
                float p = row[c2] * inv;
                row[c2] = p; arow[c2] = p;
            }
        }
    }
    __syncthreads();

    // ---- Phase 3: O = P @ V via HMMA (3-term split), warp owns 8 d-cols ----
    const uint32_t aP = sb + ATT_PH + (lane & 15) * LDP + (lane >> 4) * 16;
    const uint32_t bV = sb + ATT_KVH +
        (uint32_t)((lane & 7) + ((lane >> 3) & 1) * 8) * 144 + wid * 16;

    float oacc[4] = {};
    for (int vt = 0; vt < S; vt += KT) {
        // load V tile splits
        #pragma unroll
        for (int r = 0; r < 16; r++) {
            int row = r * 16 + (tid >> 4), c = tid & 15;
            size_t g = (size_t)(vt + row) * DK + c * 4;
            *(uint2*)(sm + ATT_KVH + row * 144 + c * 8) = *(const uint2*)(Vh + g);
            *(uint2*)(sm + ATT_KVM + row * 144 + c * 8) = *(const uint2*)(Vm + g);
        }
        // convert P tile 16x256 fp32 -> split bf16 (2048 pairs, 8 per thread)
        #pragma unroll
        for (int p = 0; p < 8; p++) {
            int idx = p * 256 + tid;
            int r = idx >> 7, c2 = (idx & 127) * 2;
            float f0 = sS[r * S + vt + c2], f1 = sS[r * S + vt + c2 + 1];
            __nv_bfloat16 h0 = __float2bfloat16(f0), h1 = __float2bfloat16(f1);
            *(__nv_bfloat162*)(sm + ATT_PH + r * LDP + c2 * 2) = __halves2bfloat162(h0, h1);
            *(__nv_bfloat162*)(sm + ATT_PM + r * LDP + c2 * 2) = __halves2bfloat162(
                __float2bfloat16(f0 - __bfloat162float(h0)),
                __float2bfloat16(f1 - __bfloat162float(h1)));
        }
        __syncthreads();

        #pragma unroll
        for (int ks = 0; ks < 16; ks++) {
            uint32_t ph[4], pm[4], vbh[2], vbm[2];
            LDSM4(ph, aP + ks * 32);
            LDSM4(pm, aP + (ATT_PM - ATT_PH) + ks * 32);
            uint32_t rv = bV + ks * (16 * 144);
            LDSM2T(vbh, rv);
            LDSM2T(vbm, rv + (ATT_KVM - ATT_KVH));
            MMA16816(oacc, ph, vbh);
            MMA16816(oacc, ph, vbm);
            MMA16816(oacc, pm, vbh);
        }
        __syncthreads();
    }

    // epilogue: write split-bf16 ctx. rows q0 + (lane>>2) and +8; cols h*64 + wid*8 + (lane&3)*2
    {
        const int b = bh >> 4, h = bh & 15;
        int r = lane >> 2;
        int c = h * DK + wid * 8 + (lane & 3) * 2;
        #pragma unroll
        for (int hp = 0; hp < 2; hp++) {
            float v0 = oacc[2*hp + 0], v1 = oacc[2*hp + 1];
            __nv_bfloat16 h0 = __float2bfloat16(v0), h1 = __float2bfloat16(v1);
            size_t o = ((size_t)(b * S) + q0 + r + 8 * hp) * D + c;
            *(__nv_bfloat162*)(g_ctx_hi + o) = __halves2bfloat162(h0, h1);
            *(__nv_bfloat162*)(g_ctx_mid + o) = __halves2bfloat162(
                __float2bfloat16(v0 - __bfloat162float(h0)),
                __float2bfloat16(v1 - __bfloat162float(h1)));
        }
    }
}

// ===================== launch =====================
extern "C" void kernel_launch(void* const* d_in, const int* in_sizes, int n_in,
                              void* d_out, int out_size)
{
    const float* query = (const float*)d_in[0];
    const float* key   = (const float*)d_in[1];
    const float* value = (const float*)d_in[2];
    const float* Wq = (const float*)d_in[3];
    const float* bq = (const float*)d_in[4];
    const float* Wk = (const float*)d_in[5];
    const float* bk = (const float*)d_in[6];
    const float* Wv = (const float*)d_in[7];
    const float* bv = (const float*)d_in[8];
    const float* Wo = (const float*)d_in[9];
    const float* bo = (const float*)d_in[10];

    float* out  = (float*)d_out;
    float* attn = out + (size_t)MROWS * D;

    cudaFuncSetAttribute(attn_kernel, cudaFuncAttributeMaxDynamicSharedMemorySize, SMEM_ATTN_BYTES);
    cudaFuncSetAttribute(qkv_mm, cudaFuncAttributeMaxDynamicSharedMemorySize, GEMM_SMEM);
    cudaFuncSetAttribute(o_mm, cudaFuncAttributeMaxDynamicSharedMemorySize, GEMM_SMEM);

    conv_acts<<<3 * MROWS * D / 4 / 256, 256>>>(query, key, value);
    conv_W<<<dim3(16, 16, 4), 256>>>(Wq, Wk, Wv, Wo);
    qkv_mm<<<dim3(8, 32, 3), 256, GEMM_SMEM>>>(bq, bk, bv);
    attn_kernel<<<dim3(S / QT, BB * H), 256, SMEM_ATTN_BYTES>>>(attn);
    o_mm<<<dim3(8, 32), 256, GEMM_SMEM>>>(bo, out);
}

// round 7
// speedup vs baseline: 2.3008x; 1.3722x over previous
#include <cuda_runtime.h>
#include <cuda_bf16.h>
#include <cstdint>

#define BB 2
#define S  2048
#define H  16
#define D  1024
#define DK 64
#define MROWS (BB*S)   // 4096

// ===================== warp-MMA helpers (sm_80+, valid on sm_103) =====================
#define LDSM4(r, a) asm volatile( \
    "ldmatrix.sync.aligned.m8n8.x4.shared.b16 {%0,%1,%2,%3}, [%4];" \
    : "=r"((r)[0]),"=r"((r)[1]),"=r"((r)[2]),"=r"((r)[3]) : "r"(a))
#define LDSM2(r, a) asm volatile( \
    "ldmatrix.sync.aligned.m8n8.x2.shared.b16 {%0,%1}, [%2];" \
    : "=r"((r)[0]),"=r"((r)[1]) : "r"(a))
#define LDSM2T(r, a) asm volatile( \
    "ldmatrix.sync.aligned.m8n8.x2.trans.shared.b16 {%0,%1}, [%2];" \
    : "=r"((r)[0]),"=r"((r)[1]) : "r"(a))
#define MMA16816(c, a, b) asm volatile( \
    "mma.sync.aligned.m16n8k16.row.col.f32.bf16.bf16.f32 " \
    "{%0,%1,%2,%3}, {%4,%5,%6,%7}, {%8,%9}, {%0,%1,%2,%3};" \
    : "+f"((c)[0]),"+f"((c)[1]),"+f"((c)[2]),"+f"((c)[3]) \
    : "r"((a)[0]),"r"((a)[1]),"r"((a)[2]),"r"((a)[3]), "r"((b)[0]),"r"((b)[1]))

__device__ __forceinline__ uint32_t smem_u32(const void* p) {
    uint32_t a;
    asm("{ .reg .u64 t; cvta.to.shared.u64 t, %1; cvt.u32.u64 %0, t; }" : "=r"(a) : "l"(p));
    return a;
}

// FFMA-pipe exp; rel err ~2e-6
__device__ __forceinline__ float fexp(float x) {
    x = fmaxf(x, -87.0f);
    float y = x * 1.44269504088896341f;
    float t = y + 12582912.0f;
    int ni = __float_as_int(t) - 0x4B400000;
    float f = y - (t - 12582912.0f);
    float p = 1.33335581464284430e-3f;
    p = fmaf(p, f, 9.61812910762847716e-3f);
    p = fmaf(p, f, 5.55041086648215800e-2f);
    p = fmaf(p, f, 2.40226506959100712e-1f);
    p = fmaf(p, f, 6.93147180559945309e-1f);
    p = fmaf(p, f, 1.0f);
    return p * __int_as_float((ni + 127) << 23);
}

// ===================== device-global scratch (16B aligned) =====================
__device__ __align__(16) __nv_bfloat16 g_Xhi [3u*MROWS*D];
__device__ __align__(16) __nv_bfloat16 g_Xmid[3u*MROWS*D];
__device__ __align__(16) __nv_bfloat16 g_WhiT [4u*D*D];   // [z][n][k] transposed
__device__ __align__(16) __nv_bfloat16 g_WmidT[4u*D*D];
__device__ __align__(16) __nv_bfloat16 g_Qh[BB*H*S*DK];
__device__ __align__(16) __nv_bfloat16 g_Qm[BB*H*S*DK];
__device__ __align__(16) __nv_bfloat16 g_Kh[BB*H*S*DK];
__device__ __align__(16) __nv_bfloat16 g_Km[BB*H*S*DK];
__device__ __align__(16) __nv_bfloat16 g_Vh[BB*H*S*DK];
__device__ __align__(16) __nv_bfloat16 g_Vm[BB*H*S*DK];
__device__ __align__(16) __nv_bfloat16 g_ctx_hi [MROWS*D];
__device__ __align__(16) __nv_bfloat16 g_ctx_mid[MROWS*D];
__device__ __align__(16) float g_rmax[BB*H*S];
__device__ __align__(16) float g_rinv[BB*H*S];

// ===================== prep: split activations =====================
__global__ __launch_bounds__(256) void conv_acts(
    const float* __restrict__ q, const float* __restrict__ k, const float* __restrict__ v)
{
    const size_t per4 = (size_t)MROWS * D / 4;
    size_t i = (size_t)blockIdx.x * 256 + threadIdx.x;
    int z = (int)(i / per4);
    size_t r = i - (size_t)z * per4;
    const float* src = (z == 0) ? q : (z == 1) ? k : v;
    float4 x = ((const float4*)src)[r];
    __nv_bfloat16 h0 = __float2bfloat16(x.x), h1 = __float2bfloat16(x.y);
    __nv_bfloat16 h2 = __float2bfloat16(x.z), h3 = __float2bfloat16(x.w);
    size_t o = i * 4;
    ((__nv_bfloat162*)(g_Xhi + o))[0] = __halves2bfloat162(h0, h1);
    ((__nv_bfloat162*)(g_Xhi + o))[1] = __halves2bfloat162(h2, h3);
    ((__nv_bfloat162*)(g_Xmid + o))[0] = __halves2bfloat162(
        __float2bfloat16(x.x - __bfloat162float(h0)), __float2bfloat16(x.y - __bfloat162float(h1)));
    ((__nv_bfloat162*)(g_Xmid + o))[1] = __halves2bfloat162(
        __float2bfloat16(x.z - __bfloat162float(h2)), __float2bfloat16(x.w - __bfloat162float(h3)));
}

// ===================== prep: split + transpose weights =====================
__global__ __launch_bounds__(256) void conv_W(
    const float* __restrict__ Wq, const float* __restrict__ Wk,
    const float* __restrict__ Wv, const float* __restrict__ Wo)
{
    __shared__ __nv_bfloat16 th[64][68];
    __shared__ __nv_bfloat16 tm[64][68];
    const int z = blockIdx.z;
    const float* src = (z == 0) ? Wq : (z == 1) ? Wk : (z == 2) ? Wv : Wo;
    const int k0 = blockIdx.y * 64, n0 = blockIdx.x * 64;
    const int t = threadIdx.x;
    #pragma unroll
    for (int p = 0; p < 4; p++) {
        int r = p * 16 + (t >> 4);
        int c4 = (t & 15) * 4;
        float4 w = *(const float4*)&src[(size_t)(k0 + r) * D + n0 + c4];
        float vv[4] = {w.x, w.y, w.z, w.w};
        #pragma unroll
        for (int j = 0; j < 4; j++) {
            __nv_bfloat16 hh = __float2bfloat16(vv[j]);
            th[c4 + j][r] = hh;
            tm[c4 + j][r] = __float2bfloat16(vv[j] - __bfloat162float(hh));
        }
    }
    __syncthreads();
    #pragma unroll
    for (int p = 0; p < 4; p++) {
        int n = p * 16 + (t >> 4);
        int k4 = (t & 15) * 4;
        size_t o = (size_t)z * D * D + (size_t)(n0 + n) * D + k0 + k4;
        *(uint2*)&g_WhiT[o]  = *(const uint2*)&th[n][k4];
        *(uint2*)&g_WmidT[o] = *(const uint2*)&tm[n][k4];
    }
}

// ===================== HMMA GEMM mainloop (128x128 CTA tile, K=1024) =====================
#define LDA 144
#define TILE_B (128*LDA)     // 18432
#define OFF_AM TILE_B
#define OFF_BH (2*TILE_B)
#define OFF_BM (3*TILE_B)
#define GEMM_SMEM (4*TILE_B) // 73728

__device__ __forceinline__ void hgemm_main(
    const __nv_bfloat16* __restrict__ Ah, const __nv_bfloat16* __restrict__ Am,
    const __nv_bfloat16* __restrict__ Bh, const __nv_bfloat16* __restrict__ Bm,
    char* smem, float acc[4][4][4])
{
    const int tid = threadIdx.x, lane = tid & 31, wid = tid >> 5;
    const int wm = wid >> 2, wn = wid & 3;
    const uint32_t sb = smem_u32(smem);

    const uint32_t a_row = (uint32_t)(wm * 64 + (lane & 15)) * LDA + (lane >> 4) * 16;
    const uint32_t b_row = (uint32_t)(wn * 32 + (lane & 7)) * LDA + ((lane >> 3) & 1) * 16;

    for (int ch = 0; ch < 16; ch++) {
        const int kb = ch * 64;
        #pragma unroll
        for (int p = 0; p < 8; p++) {
            int idx = p * 256 + tid;
            int row = idx >> 4, cg = idx & 15;
            size_t g = (size_t)row * D + kb + cg * 4;
            int so = row * LDA + cg * 8;
            *(uint2*)(smem + so)          = *(const uint2*)(Ah + g);
            *(uint2*)(smem + OFF_AM + so) = *(const uint2*)(Am + g);
            *(uint2*)(smem + OFF_BH + so) = *(const uint2*)(Bh + g);
            *(uint2*)(smem + OFF_BM + so) = *(const uint2*)(Bm + g);
        }
        __syncthreads();

        #pragma unroll
        for (int ks = 0; ks < 4; ks++) {
            uint32_t ah[4][4], am[4][4], bh[4][2], bm[4][2];
            #pragma unroll
            for (int mt = 0; mt < 4; mt++) {
                uint32_t ra = sb + a_row + mt * (16 * LDA) + ks * 32;
                LDSM4(ah[mt], ra);
                LDSM4(am[mt], ra + OFF_AM);
            }
            #pragma unroll
            for (int nt = 0; nt < 4; nt++) {
                uint32_t rb = sb + OFF_BH + b_row + nt * (8 * LDA) + ks * 32;
                LDSM2(bh[nt], rb);
                LDSM2(bm[nt], rb + (OFF_BM - OFF_BH));
            }
            #pragma unroll
            for (int mt = 0; mt < 4; mt++)
                #pragma unroll
                for (int nt = 0; nt < 4; nt++) {
                    MMA16816(acc[mt][nt], ah[mt], bh[nt]);
                    MMA16816(acc[mt][nt], ah[mt], bm[nt]);
                    MMA16816(acc[mt][nt], am[mt], bh[nt]);
                }
        }
        __syncthreads();
    }
}

// ===================== QKV GEMM: epilogue writes split bf16 head-major =====================
__global__ __launch_bounds__(256) void qkv_mm(
    const float* __restrict__ bq, const float* __restrict__ bk, const float* __restrict__ bv)
{
    extern __shared__ char smem[];
    const int z = blockIdx.z, m0 = blockIdx.y * 128, n0 = blockIdx.x * 128;
    float acc[4][4][4] = {};
    hgemm_main(g_Xhi + ((size_t)z * MROWS + m0) * D, g_Xmid + ((size_t)z * MROWS + m0) * D,
               g_WhiT + ((size_t)z * D + n0) * D,    g_WmidT + ((size_t)z * D + n0) * D,
               smem, acc);

    const float* bias = (z == 0) ? bq : (z == 1) ? bk : bv;
    __nv_bfloat16* outh = (z == 0) ? g_Qh : (z == 1) ? g_Kh : g_Vh;
    __nv_bfloat16* outm = (z == 0) ? g_Qm : (z == 1) ? g_Km : g_Vm;
    const int tid = threadIdx.x, lane = tid & 31, wid = tid >> 5;
    const int wm = wid >> 2, wn = wid & 3;
    const int g2 = lane >> 2, t4 = lane & 3;

    #pragma unroll
    for (int nt = 0; nt < 4; nt++) {
        const int c = n0 + wn * 32 + nt * 8 + 2 * t4;
        const float b0v = __ldg(&bias[c]), b1v = __ldg(&bias[c + 1]);
        const int h = c >> 6, d = c & 63;
        #pragma unroll
        for (int mt = 0; mt < 4; mt++) {
            int r0 = m0 + wm * 64 + mt * 16 + g2;
            int b = r0 >> 11, s = r0 & (S - 1);
            size_t base = ((size_t)(b * H + h) * S + s) * DK + d;
            #pragma unroll
            for (int hp = 0; hp < 2; hp++) {
                float v0 = acc[mt][nt][2*hp + 0] + b0v;
                float v1 = acc[mt][nt][2*hp + 1] + b1v;
                __nv_bfloat16 h0 = __float2bfloat16(v0), h1 = __float2bfloat16(v1);
                size_t o = base + (size_t)hp * 8 * DK;
                *(__nv_bfloat162*)(outh + o) = __halves2bfloat162(h0, h1);
                *(__nv_bfloat162*)(outm + o) = __halves2bfloat162(
                    __float2bfloat16(v0 - __bfloat162float(h0)),
                    __float2bfloat16(v1 - __bfloat162float(h1)));
            }
        }
    }
}

// ===================== O-proj GEMM (row-major epilogue) =====================
__global__ __launch_bounds__(256) void o_mm(const float* __restrict__ bo, float* __restrict__ out)
{
    extern __shared__ char smem[];
    const int m0 = blockIdx.y * 128, n0 = blockIdx.x * 128;
    float acc[4][4][4] = {};
    hgemm_main(g_ctx_hi + (size_t)m0 * D, g_ctx_mid + (size_t)m0 * D,
               g_WhiT + ((size_t)3 * D + n0) * D, g_WmidT + ((size_t)3 * D + n0) * D,
               smem, acc);

    const int tid = threadIdx.x, lane = tid & 31, wid = tid >> 5;
    const int wm = wid >> 2, wn = wid & 3;
    const int g2 = lane >> 2, t4 = lane & 3;

    #pragma unroll
    for (int nt = 0; nt < 4; nt++) {
        const int c = n0 + wn * 32 + nt * 8 + 2 * t4;
        const float b0v = __ldg(&bo[c]), b1v = __ldg(&bo[c + 1]);
        #pragma unroll
        for (int mt = 0; mt < 4; mt++) {
            int r0 = m0 + wm * 64 + mt * 16 + g2;
            float* p0 = out + (size_t)r0 * D + c;
            *(float2*)p0 = make_float2(acc[mt][nt][0] + b0v, acc[mt][nt][1] + b1v);
            float* p1 = p0 + 8 * D;
            *(float2*)p1 = make_float2(acc[mt][nt][2] + b0v, acc[mt][nt][3] + b1v);
        }
    }
}

// ===================== attention kernel 1: raw scores -> attn buffer =====================
// grid (16 n-tiles, 16 m-tiles, 32 bh), block 256, smem 73728 (Q/K split tiles)
__global__ __launch_bounds__(256) void score_mm(float* __restrict__ attn)
{
    extern __shared__ char smem[];
    const int n0 = blockIdx.x * 128, m0 = blockIdx.y * 128, bh = blockIdx.z;
    const __nv_bfloat16* Qh = g_Qh + ((size_t)bh * S + m0) * DK;
    const __nv_bfloat16* Qm = g_Qm + ((size_t)bh * S + m0) * DK;
    const __nv_bfloat16* Kh = g_Kh + ((size_t)bh * S + n0) * DK;
    const __nv_bfloat16* Km = g_Km + ((size_t)bh * S + n0) * DK;

    const int tid = threadIdx.x, lane = tid & 31, wid = tid >> 5;
    const int wm = wid >> 2, wn = wid & 3;
    const uint32_t sb = smem_u32(smem);

    #pragma unroll
    for (int p = 0; p < 8; p++) {
        int idx = p * 256 + tid;
        int row = idx >> 4, cg = idx & 15;
        size_t g = (size_t)row * DK + cg * 4;
        int so = row * LDA + cg * 8;
        *(uint2*)(smem + so)          = *(const uint2*)(Qh + g);
        *(uint2*)(smem + OFF_AM + so) = *(const uint2*)(Qm + g);
        *(uint2*)(smem + OFF_BH + so) = *(const uint2*)(Kh + g);
        *(uint2*)(smem + OFF_BM + so) = *(const uint2*)(Km + g);
    }
    __syncthreads();

    float acc[4][4][4] = {};
    const uint32_t a_row = (uint32_t)(wm * 64 + (lane & 15)) * LDA + (lane >> 4) * 16;
    const uint32_t b_row = (uint32_t)(wn * 32 + (lane & 7)) * LDA + ((lane >> 3) & 1) * 16;

    #pragma unroll
    for (int ks = 0; ks < 4; ks++) {
        uint32_t ah[4][4], am[4][4], bh_[4][2], bm_[4][2];
        #pragma unroll
        for (int mt = 0; mt < 4; mt++) {
            uint32_t ra = sb + a_row + mt * (16 * LDA) + ks * 32;
            LDSM4(ah[mt], ra);
            LDSM4(am[mt], ra + OFF_AM);
        }
        #pragma unroll
        for (int nt = 0; nt < 4; nt++) {
            uint32_t rb = sb + OFF_BH + b_row + nt * (8 * LDA) + ks * 32;
            LDSM2(bh_[nt], rb);
            LDSM2(bm_[nt], rb + (OFF_BM - OFF_BH));
        }
        #pragma unroll
        for (int mt = 0; mt < 4; mt++)
            #pragma unroll
            for (int nt = 0; nt < 4; nt++) {
                MMA16816(acc[mt][nt], ah[mt], bh_[nt]);
                MMA16816(acc[mt][nt], ah[mt], bm_[nt]);
                MMA16816(acc[mt][nt], am[mt], bh_[nt]);
            }
    }

    const int g2 = lane >> 2, t4 = lane & 3;
    #pragma unroll
    for (int nt = 0; nt < 4; nt++) {
        const int c = n0 + wn * 32 + nt * 8 + 2 * t4;
        #pragma unroll
        for (int mt = 0; mt < 4; mt++) {
            int r0 = m0 + wm * 64 + mt * 16 + g2;
            float* p0 = attn + ((size_t)bh * S + r0) * S + c;
            *(float2*)p0 = make_float2(acc[mt][nt][0] * 0.125f, acc[mt][nt][1] * 0.125f);
            float* p1 = p0 + (size_t)8 * S;
            *(float2*)p1 = make_float2(acc[mt][nt][2] * 0.125f, acc[mt][nt][3] * 0.125f);
        }
    }
}

// ===================== attention kernel 2: row max + 1/sum =====================
// grid 8192 (8 rows/CTA, warp per row), block 256
__global__ __launch_bounds__(256) void rowstat(const float* __restrict__ attn)
{
    const int row = blockIdx.x * 8 + (threadIdx.x >> 5);
    const int lane = threadIdx.x & 31;
    const float4* p = (const float4*)(attn + (size_t)row * S);

    float mx = -1e30f;
    #pragma unroll
    for (int i = 0; i < 16; i++) {
        float4 v = __ldg(p + i * 32 + lane);
        mx = fmaxf(mx, fmaxf(fmaxf(v.x, v.y), fmaxf(v.z, v.w)));
    }
    #pragma unroll
    for (int o = 16; o; o >>= 1) mx = fmaxf(mx, __shfl_xor_sync(0xffffffffu, mx, o));

    float sum = 0.f;
    #pragma unroll
    for (int i = 0; i < 16; i++) {
        float4 v = __ldg(p + i * 32 + lane);
        sum += fexp(v.x - mx) + fexp(v.y - mx) + fexp(v.z - mx) + fexp(v.w - mx);
    }
    #pragma unroll
    for (int o = 16; o; o >>= 1) sum += __shfl_xor_sync(0xffffffffu, sum, o);

    if (lane == 0) { g_rmax[row] = mx; g_rinv[row] = 1.0f / sum; }
}

// ===================== attention kernel 3: softmax-apply + PV GEMM =====================
// grid (16 m-tiles, 32 bh), block 256.
// smem: PH@0 (128x144=18432), PM@18432, VH@36864 (64x144=9216), VM@46080,
//       rmax@55296 (128 f), rinv@55808 (128 f)  -> 56320 B
#define PV_PH   0
#define PV_PM   18432
#define PV_VH   36864
#define PV_VM   46080
#define PV_RMAX 55296
#define PV_RINV 55808
#define PV_SMEM 56320

__global__ __launch_bounds__(256) void pv_mm(float* __restrict__ attn)
{
    extern __shared__ char smem[];
    const uint32_t sb = smem_u32(smem);
    float* sRmax = (float*)(smem + PV_RMAX);
    float* sRinv = (float*)(smem + PV_RINV);

    const int tid = threadIdx.x, lane = tid & 31, wid = tid >> 5;
    const int wm = wid >> 1, wn = wid & 1;          // 4x2 warps: 32 rows x 32 cols
    const int m0 = blockIdx.x * 128, bh = blockIdx.y;
    const int b = bh >> 4, h = bh & 15;

    float* attnRow = attn + ((size_t)bh * S + m0) * S;
    const __nv_bfloat16* Vh = g_Vh + (size_t)bh * S * DK;
    const __nv_bfloat16* Vm = g_Vm + (size_t)bh * S * DK;

    if (tid < 128) {
        sRmax[tid] = g_rmax[(size_t)bh * S + m0 + tid];
        sRinv[tid] = g_rinv[(size_t)bh * S + m0 + tid];
    }
    __syncthreads();

    const uint32_t a_row = sb + PV_PH + (uint32_t)(wm * 32 + (lane & 15)) * LDA + (lane >> 4) * 16;
    float acc[2][4][4] = {};

    for (int kt = 0; kt < S; kt += 64) {
        // load V chunk (64 rows x 64 cols, both splits)
        #pragma unroll
        for (int p = 0; p < 4; p++) {
            int idx = p * 256 + tid;
            int row = idx >> 4, cg = idx & 15;
            size_t g = (size_t)(kt + row) * DK + cg * 4;
            int so = row * LDA + cg * 8;
            *(uint2*)(smem + PV_VH + so) = *(const uint2*)(Vh + g);
            *(uint2*)(smem + PV_VM + so) = *(const uint2*)(Vm + g);
        }
        // P chunk: read raw, softmax-apply, write back, split-convert to smem
        #pragma unroll
        for (int p = 0; p < 8; p++) {
            int idx = p * 256 + tid;
            int r = idx >> 4, c4 = (idx & 15) * 4;
            float* gp = attnRow + (size_t)r * S + kt + c4;
            float4 v = *(const float4*)gp;
            float mx = sRmax[r], inv = sRinv[r];
            float p0 = fexp(v.x - mx) * inv, p1 = fexp(v.y - mx) * inv;
            float p2 = fexp(v.z - mx) * inv, p3 = fexp(v.w - mx) * inv;
            *(float4*)gp = make_float4(p0, p1, p2, p3);
            __nv_bfloat16 h0 = __float2bfloat16(p0), h1 = __float2bfloat16(p1);
            __nv_bfloat16 h2 = __float2bfloat16(p2), h3 = __float2bfloat16(p3);
            int so = r * LDA + c4 * 2;
            *(__nv_bfloat162*)(smem + PV_PH + so)     = __halves2bfloat162(h0, h1);
            *(__nv_bfloat162*)(smem + PV_PH + so + 4) = __halves2bfloat162(h2, h3);
            *(__nv_bfloat162*)(smem + PV_PM + so)     = __halves2bfloat162(
                __float2bfloat16(p0 - __bfloat162float(h0)), __float2bfloat16(p1 - __bfloat162float(h1)));
            *(__nv_bfloat162*)(smem + PV_PM + so + 4) = __halves2bfloat162(
                __float2bfloat16(p2 - __bfloat162float(h2)), __float2bfloat16(p3 - __bfloat162float(h3)));
        }
        __syncthreads();

        #pragma unroll
        for (int ks = 0; ks < 4; ks++) {
            uint32_t ph[2][4], pm[2][4];
            #pragma unroll
            for (int mt = 0; mt < 2; mt++) {
                uint32_t ra = a_row + mt * (16 * LDA) + ks * 32;
                LDSM4(ph[mt], ra);
                LDSM4(pm[mt], ra + (PV_PM - PV_PH));
            }
            #pragma unroll
            for (int nt = 0; nt < 4; nt++) {
                uint32_t rv = sb + PV_VH +
                    (uint32_t)(ks * 16 + (lane & 7) + ((lane >> 3) & 1) * 8) * LDA +
                    (wn * 32 + nt * 8) * 2;
                uint32_t vbh[2], vbm[2];
                LDSM2T(vbh, rv);
                LDSM2T(vbm, rv + (PV_VM - PV_VH));
                #pragma unroll
                for (int mt = 0; mt < 2; mt++) {
                    MMA16816(acc[mt][nt], ph[mt], vbh);
                    MMA16816(acc[mt][nt], ph[mt], vbm);
                    MMA16816(acc[mt][nt], pm[mt], vbh);
                }
            }
        }
        __syncthreads();
    }

    // epilogue: split-bf16 ctx write
    const int g2 = lane >> 2, t4 = lane & 3;
    #pragma unroll
    for (int nt = 0; nt < 4; nt++) {
        const int c = h * DK + wn * 32 + nt * 8 + 2 * t4;
        #pragma unroll
        for (int mt = 0; mt < 2; mt++) {
            int r0 = m0 + wm * 32 + mt * 16 + g2;
            #pragma unroll
            for (int hp = 0; hp < 2; hp++) {
                float v0 = acc[mt][nt][2*hp + 0], v1 = acc[mt][nt][2*hp + 1];
                __nv_bfloat16 h0 = __float2bfloat16(v0), h1 = __float2bfloat16(v1);
                size_t o = ((size_t)(b * S) + r0 + 8 * hp) * D + c;
                *(__nv_bfloat162*)(g_ctx_hi + o) = __halves2bfloat162(h0, h1);
                *(__nv_bfloat162*)(g_ctx_mid + o) = __halves2bfloat162(
                    __float2bfloat16(v0 - __bfloat162float(h0)),
                    __float2bfloat16(v1 - __bfloat162float(h1)));
            }
        }
    }
}

// ===================== launch =====================
extern "C" void kernel_launch(void* const* d_in, const int* in_sizes, int n_in,
                              void* d_out, int out_size)
{
    const float* query = (const float*)d_in[0];
    const float* key   = (const float*)d_in[1];
    const float* value = (const float*)d_in[2];
    const float* Wq = (const float*)d_in[3];
    const float* bq = (const float*)d_in[4];
    const float* Wk = (const float*)d_in[5];
    const float* bk = (const float*)d_in[6];
    const float* Wv = (const float*)d_in[7];
    const float* bv = (const float*)d_in[8];
    const float* Wo = (const float*)d_in[9];
    const float* bo = (const float*)d_in[10];

    float* out  = (float*)d_out;
    float* attn = out + (size_t)MROWS * D;

    cudaFuncSetAttribute(qkv_mm, cudaFuncAttributeMaxDynamicSharedMemorySize, GEMM_SMEM);
    cudaFuncSetAttribute(o_mm, cudaFuncAttributeMaxDynamicSharedMemorySize, GEMM_SMEM);
    cudaFuncSetAttribute(score_mm, cudaFuncAttributeMaxDynamicSharedMemorySize, GEMM_SMEM);
    cudaFuncSetAttribute(pv_mm, cudaFuncAttributeMaxDynamicSharedMemorySize, PV_SMEM);

    conv_acts<<<3 * MROWS * D / 4 / 256, 256>>>(query, key, value);
    conv_W<<<dim3(16, 16, 4), 256>>>(Wq, Wk, Wv, Wo);
    qkv_mm<<<dim3(8, 32, 3), 256, GEMM_SMEM>>>(bq, bk, bv);
    score_mm<<<dim3(16, 16, 32), 256, GEMM_SMEM>>>(attn);
    rowstat<<<BB * H * S / 8, 256>>>(attn);
    pv_mm<<<dim3(16, 32), 256, PV_SMEM>>>(attn);
    o_mm<<<dim3(8, 32), 256, GEMM_SMEM>>>(bo, out);
}

// round 8
// speedup vs baseline: 2.5838x; 1.1230x over previous
#include <cuda_runtime.h>
#include <cuda_bf16.h>
#include <cstdint>

#define BB 2
#define S  2048
#define H  16
#define D  1024
#define DK 64
#define MROWS (BB*S)   // 4096

// ===================== warp-MMA helpers (sm_80+, valid on sm_103) =====================
#define LDSM4(r, a) asm volatile( \
    "ldmatrix.sync.aligned.m8n8.x4.shared.b16 {%0,%1,%2,%3}, [%4];" \
    : "=r"((r)[0]),"=r"((r)[1]),"=r"((r)[2]),"=r"((r)[3]) : "r"(a))
#define LDSM2(r, a) asm volatile( \
    "ldmatrix.sync.aligned.m8n8.x2.shared.b16 {%0,%1}, [%2];" \
    : "=r"((r)[0]),"=r"((r)[1]) : "r"(a))
#define LDSM2T(r, a) asm volatile( \
    "ldmatrix.sync.aligned.m8n8.x2.trans.shared.b16 {%0,%1}, [%2];" \
    : "=r"((r)[0]),"=r"((r)[1]) : "r"(a))
#define MMA16816(c, a, b) asm volatile( \
    "mma.sync.aligned.m16n8k16.row.col.f32.bf16.bf16.f32 " \
    "{%0,%1,%2,%3}, {%4,%5,%6,%7}, {%8,%9}, {%0,%1,%2,%3};" \
    : "+f"((c)[0]),"+f"((c)[1]),"+f"((c)[2]),"+f"((c)[3]) \
    : "r"((a)[0]),"r"((a)[1]),"r"((a)[2]),"r"((a)[3]), "r"((b)[0]),"r"((b)[1]))

__device__ __forceinline__ uint32_t smem_u32(const void* p) {
    uint32_t a;
    asm("{ .reg .u64 t; cvta.to.shared.u64 t, %1; cvt.u32.u64 %0, t; }" : "=r"(a) : "l"(p));
    return a;
}

// FFMA-pipe exp; rel err ~2e-6
__device__ __forceinline__ float fexp(float x) {
    x = fmaxf(x, -87.0f);
    float y = x * 1.44269504088896341f;
    float t = y + 12582912.0f;
    int ni = __float_as_int(t) - 0x4B400000;
    float f = y - (t - 12582912.0f);
    float p = 1.33335581464284430e-3f;
    p = fmaf(p, f, 9.61812910762847716e-3f);
    p = fmaf(p, f, 5.55041086648215800e-2f);
    p = fmaf(p, f, 2.40226506959100712e-1f);
    p = fmaf(p, f, 6.93147180559945309e-1f);
    p = fmaf(p, f, 1.0f);
    return p * __int_as_float((ni + 127) << 23);
}

// ===================== device-global scratch (16B aligned) =====================
__device__ __align__(16) __nv_bfloat16 g_Xhi [3u*MROWS*D];
__device__ __align__(16) __nv_bfloat16 g_Xmid[3u*MROWS*D];
__device__ __align__(16) __nv_bfloat16 g_WhiT [4u*D*D];   // [z][n][k] transposed
__device__ __align__(16) __nv_bfloat16 g_WmidT[4u*D*D];
__device__ __align__(16) __nv_bfloat16 g_Qh[BB*H*S*DK];
__device__ __align__(16) __nv_bfloat16 g_Qm[BB*H*S*DK];
__device__ __align__(16) __nv_bfloat16 g_Kh[BB*H*S*DK];
__device__ __align__(16) __nv_bfloat16 g_Km[BB*H*S*DK];
__device__ __align__(16) __nv_bfloat16 g_Vh[BB*H*S*DK];
__device__ __align__(16) __nv_bfloat16 g_Vm[BB*H*S*DK];
__device__ __align__(16) __nv_bfloat16 g_ctx_hi [MROWS*D];
__device__ __align__(16) __nv_bfloat16 g_ctx_mid[MROWS*D];
__device__ __align__(16) float g_rmax[BB*H*S];
__device__ __align__(16) float g_rinv[BB*H*S];

// ===================== prep: split activations =====================
__global__ __launch_bounds__(256) void conv_acts(
    const float* __restrict__ q, const float* __restrict__ k, const float* __restrict__ v)
{
    const size_t per4 = (size_t)MROWS * D / 4;
    size_t i = (size_t)blockIdx.x * 256 + threadIdx.x;
    int z = (int)(i / per4);
    size_t r = i - (size_t)z * per4;
    const float* src = (z == 0) ? q : (z == 1) ? k : v;
    float4 x = ((const float4*)src)[r];
    __nv_bfloat16 h0 = __float2bfloat16(x.x), h1 = __float2bfloat16(x.y);
    __nv_bfloat16 h2 = __float2bfloat16(x.z), h3 = __float2bfloat16(x.w);
    size_t o = i * 4;
    ((__nv_bfloat162*)(g_Xhi + o))[0] = __halves2bfloat162(h0, h1);
    ((__nv_bfloat162*)(g_Xhi + o))[1] = __halves2bfloat162(h2, h3);
    ((__nv_bfloat162*)(g_Xmid + o))[0] = __halves2bfloat162(
        __float2bfloat16(x.x - __bfloat162float(h0)), __float2bfloat16(x.y - __bfloat162float(h1)));
    ((__nv_bfloat162*)(g_Xmid + o))[1] = __halves2bfloat162(
        __float2bfloat16(x.z - __bfloat162float(h2)), __float2bfloat16(x.w - __bfloat162float(h3)));
}

// ===================== prep: split + transpose weights =====================
__global__ __launch_bounds__(256) void conv_W(
    const float* __restrict__ Wq, const float* __restrict__ Wk,
    const float* __restrict__ Wv, const float* __restrict__ Wo)
{
    __shared__ __nv_bfloat16 th[64][68];
    __shared__ __nv_bfloat16 tm[64][68];
    const int z = blockIdx.z;
    const float* src = (z == 0) ? Wq : (z == 1) ? Wk : (z == 2) ? Wv : Wo;
    const int k0 = blockIdx.y * 64, n0 = blockIdx.x * 64;
    const int t = threadIdx.x;
    #pragma unroll
    for (int p = 0; p < 4; p++) {
        int r = p * 16 + (t >> 4);
        int c4 = (t & 15) * 4;
        float4 w = *(const float4*)&src[(size_t)(k0 + r) * D + n0 + c4];
        float vv[4] = {w.x, w.y, w.z, w.w};
        #pragma unroll
        for (int j = 0; j < 4; j++) {
            __nv_bfloat16 hh = __float2bfloat16(vv[j]);
            th[c4 + j][r] = hh;
            tm[c4 + j][r] = __float2bfloat16(vv[j] - __bfloat162float(hh));
        }
    }
    __syncthreads();
    #pragma unroll
    for (int p = 0; p < 4; p++) {
        int n = p * 16 + (t >> 4);
        int k4 = (t & 15) * 4;
        size_t o = (size_t)z * D * D + (size_t)(n0 + n) * D + k0 + k4;
        *(uint2*)&g_WhiT[o]  = *(const uint2*)&th[n][k4];
        *(uint2*)&g_WmidT[o] = *(const uint2*)&tm[n][k4];
    }
}

// ===================== HMMA GEMM mainloop (128x128 CTA tile, K=1024) =====================
#define LDA 144
#define TILE_B (128*LDA)     // 18432
#define OFF_AM TILE_B
#define OFF_BH (2*TILE_B)
#define OFF_BM (3*TILE_B)
#define GEMM_SMEM (4*TILE_B) // 73728

__device__ __forceinline__ void hgemm_main(
    const __nv_bfloat16* __restrict__ Ah, const __nv_bfloat16* __restrict__ Am,
    const __nv_bfloat16* __restrict__ Bh, const __nv_bfloat16* __restrict__ Bm,
    char* smem, float acc[4][4][4])
{
    const int tid = threadIdx.x, lane = tid & 31, wid = tid >> 5;
    const int wm = wid >> 2, wn = wid & 3;
    const uint32_t sb = smem_u32(smem);

    const uint32_t a_row = (uint32_t)(wm * 64 + (lane & 15)) * LDA + (lane >> 4) * 16;
    const uint32_t b_row = (uint32_t)(wn * 32 + (lane & 7)) * LDA + ((lane >> 3) & 1) * 16;

    for (int ch = 0; ch < 16; ch++) {
        const int kb = ch * 64;
        #pragma unroll
        for (int p = 0; p < 8; p++) {
            int idx = p * 256 + tid;
            int row = idx >> 4, cg = idx & 15;
            size_t g = (size_t)row * D + kb + cg * 4;
            int so = row * LDA + cg * 8;
            *(uint2*)(smem + so)          = *(const uint2*)(Ah + g);
            *(uint2*)(smem + OFF_AM + so) = *(const uint2*)(Am + g);
            *(uint2*)(smem + OFF_BH + so) = *(const uint2*)(Bh + g);
            *(uint2*)(smem + OFF_BM + so) = *(const uint2*)(Bm + g);
        }
        __syncthreads();

        #pragma unroll
        for (int ks = 0; ks < 4; ks++) {
            uint32_t ah[4][4], am[4][4], bh[4][2], bm[4][2];
            #pragma unroll
            for (int mt = 0; mt < 4; mt++) {
                uint32_t ra = sb + a_row + mt * (16 * LDA) + ks * 32;
                LDSM4(ah[mt], ra);
                LDSM4(am[mt], ra + OFF_AM);
            }
            #pragma unroll
            for (int nt = 0; nt < 4; nt++) {
                uint32_t rb = sb + OFF_BH + b_row + nt * (8 * LDA) + ks * 32;
                LDSM2(bh[nt], rb);
                LDSM2(bm[nt], rb + (OFF_BM - OFF_BH));
            }
            #pragma unroll
            for (int mt = 0; mt < 4; mt++)
                #pragma unroll
                for (int nt = 0; nt < 4; nt++) {
                    MMA16816(acc[mt][nt], ah[mt], bh[nt]);
                    MMA16816(acc[mt][nt], ah[mt], bm[nt]);
                    MMA16816(acc[mt][nt], am[mt], bh[nt]);
                }
        }
        __syncthreads();
    }
}

// ===================== QKV GEMM: epilogue writes split bf16 head-major =====================
__global__ __launch_bounds__(256) void qkv_mm(
    const float* __restrict__ bq, const float* __restrict__ bk, const float* __restrict__ bv)
{
    extern __shared__ char smem[];
    const int z = blockIdx.z, m0 = blockIdx.y * 128, n0 = blockIdx.x * 128;
    float acc[4][4][4] = {};
    hgemm_main(g_Xhi + ((size_t)z * MROWS + m0) * D, g_Xmid + ((size_t)z * MROWS + m0) * D,
               g_WhiT + ((size_t)z * D + n0) * D,    g_WmidT + ((size_t)z * D + n0) * D,
               smem, acc);

    const float* bias = (z == 0) ? bq : (z == 1) ? bk : bv;
    __nv_bfloat16* outh = (z == 0) ? g_Qh : (z == 1) ? g_Kh : g_Vh;
    __nv_bfloat16* outm = (z == 0) ? g_Qm : (z == 1) ? g_Km : g_Vm;
    const int tid = threadIdx.x, lane = tid & 31, wid = tid >> 5;
    const int wm = wid >> 2, wn = wid & 3;
    const int g2 = lane >> 2, t4 = lane & 3;

    #pragma unroll
    for (int nt = 0; nt < 4; nt++) {
        const int c = n0 + wn * 32 + nt * 8 + 2 * t4;
        const float b0v = __ldg(&bias[c]), b1v = __ldg(&bias[c + 1]);
        const int h = c >> 6, d = c & 63;
        #pragma unroll
        for (int mt = 0; mt < 4; mt++) {
            int r0 = m0 + wm * 64 + mt * 16 + g2;
            int b = r0 >> 11, s = r0 & (S - 1);
            size_t base = ((size_t)(b * H + h) * S + s) * DK + d;
            #pragma unroll
            for (int hp = 0; hp < 2; hp++) {
                float v0 = acc[mt][nt][2*hp + 0] + b0v;
                float v1 = acc[mt][nt][2*hp + 1] + b1v;
                __nv_bfloat16 h0 = __float2bfloat16(v0), h1 = __float2bfloat16(v1);
                size_t o = base + (size_t)hp * 8 * DK;
                *(__nv_bfloat162*)(outh + o) = __halves2bfloat162(h0, h1);
                *(__nv_bfloat162*)(outm + o) = __halves2bfloat162(
                    __float2bfloat16(v0 - __bfloat162float(h0)),
                    __float2bfloat16(v1 - __bfloat162float(h1)));
            }
        }
    }
}

// ===================== O-proj GEMM (row-major epilogue) =====================
__global__ __launch_bounds__(256) void o_mm(const float* __restrict__ bo, float* __restrict__ out)
{
    extern __shared__ char smem[];
    const int m0 = blockIdx.y * 128, n0 = blockIdx.x * 128;
    float acc[4][4][4] = {};
    hgemm_main(g_ctx_hi + (size_t)m0 * D, g_ctx_mid + (size_t)m0 * D,
               g_WhiT + ((size_t)3 * D + n0) * D, g_WmidT + ((size_t)3 * D + n0) * D,
               smem, acc);

    const int tid = threadIdx.x, lane = tid & 31, wid = tid >> 5;
    const int wm = wid >> 2, wn = wid & 3;
    const int g2 = lane >> 2, t4 = lane & 3;

    #pragma unroll
    for (int nt = 0; nt < 4; nt++) {
        const int c = n0 + wn * 32 + nt * 8 + 2 * t4;
        const float b0v = __ldg(&bo[c]), b1v = __ldg(&bo[c + 1]);
        #pragma unroll
        for (int mt = 0; mt < 4; mt++) {
            int r0 = m0 + wm * 64 + mt * 16 + g2;
            float* p0 = out + (size_t)r0 * D + c;
            *(float2*)p0 = make_float2(acc[mt][nt][0] + b0v, acc[mt][nt][1] + b1v);
            float* p1 = p0 + 8 * D;
            *(float2*)p1 = make_float2(acc[mt][nt][2] + b0v, acc[mt][nt][3] + b1v);
        }
    }
}

// ===================== attention kernel 1: online softmax stats (no attn I/O) ==========
// grid (16 m-tiles, 32 bh), block 256. Warp layout 4x2 (rows x cols).
// smem: QH@0 (18432), QM@18432, KH@36864 (9216), KM@46080 -> 55296
#define ST_QH 0
#define ST_QM 18432
#define ST_KH 36864
#define ST_KM 46080
#define ST_SMEM 55296

__global__ __launch_bounds__(256) void stats_mm()
{
    extern __shared__ char smem[];
    const uint32_t sb = smem_u32(smem);
    const int tid = threadIdx.x, lane = tid & 31, wid = tid >> 5;
    const int wm = wid >> 1, wn = wid & 1;
    const int g2 = lane >> 2, t4 = lane & 3;
    const int q0 = blockIdx.x * 128, bh = blockIdx.y;

    const __nv_bfloat16* Qh = g_Qh + ((size_t)bh * S + q0) * DK;
    const __nv_bfloat16* Qm = g_Qm + ((size_t)bh * S + q0) * DK;
    const __nv_bfloat16* Kh = g_Kh + (size_t)bh * S * DK;
    const __nv_bfloat16* Km = g_Km + (size_t)bh * S * DK;

    // load Q tile
    #pragma unroll
    for (int p = 0; p < 8; p++) {
        int idx = p * 256 + tid;
        int row = idx >> 4, cg = idx & 15;
        size_t g = (size_t)row * DK + cg * 4;
        int so = row * LDA + cg * 8;
        *(uint2*)(smem + ST_QH + so) = *(const uint2*)(Qh + g);
        *(uint2*)(smem + ST_QM + so) = *(const uint2*)(Qm + g);
    }

    const uint32_t aQ = sb + ST_QH + (uint32_t)(wm * 32 + (lane & 15)) * LDA + (lane >> 4) * 16;
    const uint32_t bK = sb + ST_KH + (uint32_t)(wn * 32 + (lane & 7)) * LDA + ((lane >> 3) & 1) * 16;

    float mst[2][2] = {{-1e30f,-1e30f},{-1e30f,-1e30f}};
    float sst[2][2] = {};

    for (int kt = 0; kt < S; kt += 64) {
        #pragma unroll
        for (int p = 0; p < 4; p++) {
            int idx = p * 256 + tid;
            int row = idx >> 4, cg = idx & 15;
            size_t g = (size_t)(kt + row) * DK + cg * 4;
            int so = row * LDA + cg * 8;
            *(uint2*)(smem + ST_KH + so) = *(const uint2*)(Kh + g);
            *(uint2*)(smem + ST_KM + so) = *(const uint2*)(Km + g);
        }
        __syncthreads();

        float sacc[2][4][4] = {};
        #pragma unroll
        for (int ks = 0; ks < 4; ks++) {
            uint32_t qh[2][4], qm[2][4], kbh[4][2], kbm[4][2];
            #pragma unroll
            for (int mt = 0; mt < 2; mt++) {
                uint32_t ra = aQ + mt * (16 * LDA) + ks * 32;
                LDSM4(qh[mt], ra);
                LDSM4(qm[mt], ra + (ST_QM - ST_QH));
            }
            #pragma unroll
            for (int nt = 0; nt < 4; nt++) {
                uint32_t rb = bK + nt * (8 * LDA) + ks * 32;
                LDSM2(kbh[nt], rb);
                LDSM2(kbm[nt], rb + (ST_KM - ST_KH));
                #pragma unroll
                for (int mt = 0; mt < 2; mt++) {
                    MMA16816(sacc[mt][nt], qh[mt], kbh[nt]);
                    MMA16816(sacc[mt][nt], qh[mt], kbm[nt]);
                    MMA16816(sacc[mt][nt], qm[mt], kbh[nt]);
                }
            }
        }
        // online stats update
        #pragma unroll
        for (int mt = 0; mt < 2; mt++)
            #pragma unroll
            for (int hp = 0; hp < 2; hp++) {
                float v[8];
                #pragma unroll
                for (int nt = 0; nt < 4; nt++) {
                    v[2*nt]   = sacc[mt][nt][2*hp]     * 0.125f;
                    v[2*nt+1] = sacc[mt][nt][2*hp + 1] * 0.125f;
                }
                float mc = v[0];
                #pragma unroll
                for (int i = 1; i < 8; i++) mc = fmaxf(mc, v[i]);
                mc = fmaxf(mc, __shfl_xor_sync(0xffffffffu, mc, 1));
                mc = fmaxf(mc, __shfl_xor_sync(0xffffffffu, mc, 2));
                float mn = fmaxf(mst[mt][hp], mc);
                float ps = 0.f;
                #pragma unroll
                for (int i = 0; i < 8; i++) ps += fexp(v[i] - mn);
                ps += __shfl_xor_sync(0xffffffffu, ps, 1);
                ps += __shfl_xor_sync(0xffffffffu, ps, 2);
                sst[mt][hp] = sst[mt][hp] * fexp(mst[mt][hp] - mn) + ps;
                mst[mt][hp] = mn;
            }
        __syncthreads();
    }

    // combine across the two wn warps via smem
    float* sbuf = (float*)(smem + ST_KH);
    if (t4 == 0) {
        #pragma unroll
        for (int mt = 0; mt < 2; mt++)
            #pragma unroll
            for (int hp = 0; hp < 2; hp++) {
                int r = wm * 32 + mt * 16 + g2 + 8 * hp;
                sbuf[wn * 256 + r * 2]     = mst[mt][hp];
                sbuf[wn * 256 + r * 2 + 1] = sst[mt][hp];
            }
    }
    __syncthreads();
    if (tid < 128) {
        float m0 = sbuf[tid * 2], s0 = sbuf[tid * 2 + 1];
        float m1 = sbuf[256 + tid * 2], s1 = sbuf[256 + tid * 2 + 1];
        float M = fmaxf(m0, m1);
        float Ss = s0 * fexp(m0 - M) + s1 * fexp(m1 - M);
        size_t r = (size_t)bh * S + q0 + tid;
        g_rmax[r] = M;
        g_rinv[r] = 1.0f / Ss;
    }
}

// ===================== attention kernel 2: fused softmax-apply + PV ==================
// grid (16 m-tiles, 32 bh), block 256. Warp layout 4x2.
// smem: QH@0, QM@18432, KH@36864, KM@46080, VH@55296, VM@64512,
//       PH@73728, PM@92160, RMAX@110592, RINV@111104  -> 111616
#define FB_QH   0
#define FB_QM   18432
#define FB_KH   36864
#define FB_KM   46080
#define FB_VH   55296
#define FB_VM   64512
#define FB_PH   73728
#define FB_PM   92160
#define FB_RMAX 110592
#define FB_RINV 111104
#define FB_SMEM 111616

__global__ __launch_bounds__(256) void fused_pv(float* __restrict__ attn)
{
    extern __shared__ char smem[];
    const uint32_t sb = smem_u32(smem);
    float* sRmax = (float*)(smem + FB_RMAX);
    float* sRinv = (float*)(smem + FB_RINV);

    const int tid = threadIdx.x, lane = tid & 31, wid = tid >> 5;
    const int wm = wid >> 1, wn = wid & 1;
    const int g2 = lane >> 2, t4 = lane & 3;
    const int q0 = blockIdx.x * 128, bh = blockIdx.y;
    const int b = bh >> 4, h = bh & 15;

    const __nv_bfloat16* Qh = g_Qh + ((size_t)bh * S + q0) * DK;
    const __nv_bfloat16* Qm = g_Qm + ((size_t)bh * S + q0) * DK;
    const __nv_bfloat16* Kh = g_Kh + (size_t)bh * S * DK;
    const __nv_bfloat16* Km = g_Km + (size_t)bh * S * DK;
    const __nv_bfloat16* Vh = g_Vh + (size_t)bh * S * DK;
    const __nv_bfloat16* Vm = g_Vm + (size_t)bh * S * DK;
    float* attnBase = attn + ((size_t)bh * S + q0) * S;

    // load Q tile + stats
    #pragma unroll
    for (int p = 0; p < 8; p++) {
        int idx = p * 256 + tid;
        int row = idx >> 4, cg = idx & 15;
        size_t g = (size_t)row * DK + cg * 4;
        int so = row * LDA + cg * 8;
        *(uint2*)(smem + FB_QH + so) = *(const uint2*)(Qh + g);
        *(uint2*)(smem + FB_QM + so) = *(const uint2*)(Qm + g);
    }
    if (tid < 128) {
        sRmax[tid] = g_rmax[(size_t)bh * S + q0 + tid];
        sRinv[tid] = g_rinv[(size_t)bh * S + q0 + tid];
    }

    const uint32_t aQ = sb + FB_QH + (uint32_t)(wm * 32 + (lane & 15)) * LDA + (lane >> 4) * 16;
    const uint32_t bK = sb + FB_KH + (uint32_t)(wn * 32 + (lane & 7)) * LDA + ((lane >> 3) & 1) * 16;
    const uint32_t aP = sb + FB_PH + (uint32_t)(wm * 32 + (lane & 15)) * LDA + (lane >> 4) * 16;
    const uint32_t bV = sb + FB_VH + (uint32_t)((lane & 7) + ((lane >> 3) & 1) * 8) * LDA + wn * 64;

    float pacc[2][4][4] = {};

    for (int kt = 0; kt < S; kt += 64) {
        // load K + V chunks (both splits)
        #pragma unroll
        for (int p = 0; p < 4; p++) {
            int idx = p * 256 + tid;
            int row = idx >> 4, cg = idx & 15;
            size_t g = (size_t)(kt + row) * DK + cg * 4;
            int so = row * LDA + cg * 8;
            *(uint2*)(smem + FB_KH + so) = *(const uint2*)(Kh + g);
            *(uint2*)(smem + FB_KM + so) = *(const uint2*)(Km + g);
            *(uint2*)(smem + FB_VH + so) = *(const uint2*)(Vh + g);
            *(uint2*)(smem + FB_VM + so) = *(const uint2*)(Vm + g);
        }
        __syncthreads();

        // scores
        float sacc[2][4][4] = {};
        #pragma unroll
        for (int ks = 0; ks < 4; ks++) {
            uint32_t qh[2][4], qm[2][4], kbh[4][2], kbm[4][2];
            #pragma unroll
            for (int mt = 0; mt < 2; mt++) {
                uint32_t ra = aQ + mt * (16 * LDA) + ks * 32;
                LDSM4(qh[mt], ra);
                LDSM4(qm[mt], ra + (FB_QM - FB_QH));
            }
            #pragma unroll
            for (int nt = 0; nt < 4; nt++) {
                uint32_t rb = bK + nt * (8 * LDA) + ks * 32;
                LDSM2(kbh[nt], rb);
                LDSM2(kbm[nt], rb + (FB_KM - FB_KH));
                #pragma unroll
                for (int mt = 0; mt < 2; mt++) {
                    MMA16816(sacc[mt][nt], qh[mt], kbh[nt]);
                    MMA16816(sacc[mt][nt], qh[mt], kbm[nt]);
                    MMA16816(sacc[mt][nt], qm[mt], kbh[nt]);
                }
            }
        }

        // softmax-apply: write probs to attn + split-bf16 P to smem
        #pragma unroll
        for (int mt = 0; mt < 2; mt++) {
            int rl0 = wm * 32 + mt * 16 + g2;
            float mx0 = sRmax[rl0],     iv0 = sRinv[rl0];
            float mx1 = sRmax[rl0 + 8], iv1 = sRinv[rl0 + 8];
            #pragma unroll
            for (int nt = 0; nt < 4; nt++) {
                int cl = wn * 32 + nt * 8 + t4 * 2;
                float p00 = fexp(sacc[mt][nt][0] * 0.125f - mx0) * iv0;
                float p01 = fexp(sacc[mt][nt][1] * 0.125f - mx0) * iv0;
                float p10 = fexp(sacc[mt][nt][2] * 0.125f - mx1) * iv1;
                float p11 = fexp(sacc[mt][nt][3] * 0.125f - mx1) * iv1;
                *(float2*)(attnBase + (size_t)rl0 * S + kt + cl)       = make_float2(p00, p01);
                *(float2*)(attnBase + (size_t)(rl0 + 8) * S + kt + cl) = make_float2(p10, p11);
                __nv_bfloat16 h00 = __float2bfloat16(p00), h01 = __float2bfloat16(p01);
                __nv_bfloat16 h10 = __float2bfloat16(p10), h11 = __float2bfloat16(p11);
                *(__nv_bfloat162*)(smem + FB_PH + rl0 * LDA + cl * 2) = __halves2bfloat162(h00, h01);
                *(__nv_bfloat162*)(smem + FB_PH + (rl0 + 8) * LDA + cl * 2) = __halves2bfloat162(h10, h11);
                *(__nv_bfloat162*)(smem + FB_PM + rl0 * LDA + cl * 2) = __halves2bfloat162(
                    __float2bfloat16(p00 - __bfloat162float(h00)),
                    __float2bfloat16(p01 - __bfloat162float(h01)));
                *(__nv_bfloat162*)(smem + FB_PM + (rl0 + 8) * LDA + cl * 2) = __halves2bfloat162(
                    __float2bfloat16(p10 - __bfloat162float(h10)),
                    __float2bfloat16(p11 - __bfloat162float(h11)));
            }
        }
        __syncthreads();

        // PV MMA
        #pragma unroll
        for (int ks = 0; ks < 4; ks++) {
            uint32_t ph[2][4], pm[2][4];
            #pragma unroll
            for (int mt = 0; mt < 2; mt++) {
                uint32_t ra = aP + mt * (16 * LDA) + ks * 32;
                LDSM4(ph[mt], ra);
                LDSM4(pm[mt], ra + (FB_PM - FB_PH));
            }
            #pragma unroll
            for (int nt = 0; nt < 4; nt++) {
                uint32_t rv = bV + ks * (16 * LDA) + nt * 16;
                uint32_t vh2[2], vm2[2];
                LDSM2T(vh2, rv);
                LDSM2T(vm2, rv + (FB_VM - FB_VH));
                #pragma unroll
                for (int mt = 0; mt < 2; mt++) {
                    MMA16816(pacc[mt][nt], ph[mt], vh2);
                    MMA16816(pacc[mt][nt], ph[mt], vm2);
                    MMA16816(pacc[mt][nt], pm[mt], vh2);
                }
            }
        }
        __syncthreads();
    }

    // ctx epilogue: split-bf16
    #pragma unroll
    for (int nt = 0; nt < 4; nt++) {
        const int c = h * DK + wn * 32 + nt * 8 + 2 * t4;
        #pragma unroll
        for (int mt = 0; mt < 2; mt++) {
            int r0 = q0 + wm * 32 + mt * 16 + g2;
            #pragma unroll
            for (int hp = 0; hp < 2; hp++) {
                float v0 = pacc[mt][nt][2*hp + 0], v1 = pacc[mt][nt][2*hp + 1];
                __nv_bfloat16 h0 = __float2bfloat16(v0), h1 = __float2bfloat16(v1);
                size_t o = ((size_t)(b * S) + r0 + 8 * hp) * D + c;
                *(__nv_bfloat162*)(g_ctx_hi + o) = __halves2bfloat162(h0, h1);
                *(__nv_bfloat162*)(g_ctx_mid + o) = __halves2bfloat162(
                    __float2bfloat16(v0 - __bfloat162float(h0)),
                    __float2bfloat16(v1 - __bfloat162float(h1)));
            }
        }
    }
}

// ===================== launch =====================
extern "C" void kernel_launch(void* const* d_in, const int* in_sizes, int n_in,
                              void* d_out, int out_size)
{
    const float* query = (const float*)d_in[0];
    const float* key   = (const float*)d_in[1];
    const float* value = (const float*)d_in[2];
    const float* Wq = (const float*)d_in[3];
    const float* bq = (const float*)d_in[4];
    const float* Wk = (const float*)d_in[5];
    const float* bk = (const float*)d_in[6];
    const float* Wv = (const float*)d_in[7];
    const float* bv = (const float*)d_in[8];
    const float* Wo = (const float*)d_in[9];
    const float* bo = (const float*)d_in[10];

    float* out  = (float*)d_out;
    float* attn = out + (size_t)MROWS * D;

    cudaFuncSetAttribute(qkv_mm, cudaFuncAttributeMaxDynamicSharedMemorySize, GEMM_SMEM);
    cudaFuncSetAttribute(o_mm, cudaFuncAttributeMaxDynamicSharedMemorySize, GEMM_SMEM);
    cudaFuncSetAttribute(stats_mm, cudaFuncAttributeMaxDynamicSharedMemorySize, ST_SMEM);
    cudaFuncSetAttribute(fused_pv, cudaFuncAttributeMaxDynamicSharedMemorySize, FB_SMEM);

    conv_acts<<<3 * MROWS * D / 4 / 256, 256>>>(query, key, value);
    conv_W<<<dim3(16, 16, 4), 256>>>(Wq, Wk, Wv, Wo);
    qkv_mm<<<dim3(8, 32, 3), 256, GEMM_SMEM>>>(bq, bk, bv);
    stats_mm<<<dim3(16, 32), 256, ST_SMEM>>>();
    fused_pv<<<dim3(16, 32), 256, FB_SMEM>>>(attn);
    o_mm<<<dim3(8, 32), 256, GEMM_SMEM>>>(bo, out);
}